// round 1
// baseline (speedup 1.0000x reference)
#include <cuda_runtime.h>
#include <math.h>

#define PP 8192
#define DDIM 512

// ---- scratch (device globals: allocation-free per harness rules) ----
__device__ float g_Q[PP * DDIM];
__device__ float g_K[PP * DDIM];
__device__ float g_V[PP * DDIM];
__device__ float g_norm[PP];
__device__ float g_inv[PP];
__device__ float g_T[(size_t)PP * PP];   // 256 MB: logits - lam*dist, then exp(...)

// ============================================================
// Kernel 1: Q/K/V = F @ W^T + b  (three outputs, shared F tile)
// 64x64 tile, 256 threads, 4x4 per thread, BK=16
// ============================================================
__global__ __launch_bounds__(256) void qkv_kernel(
    const float* __restrict__ F,
    const float* __restrict__ Wq, const float* __restrict__ bq,
    const float* __restrict__ Wk, const float* __restrict__ bk,
    const float* __restrict__ Wv, const float* __restrict__ bv)
{
    const int BK = 16;
    __shared__ float Fs[BK][64];
    __shared__ float Qw[BK][64];
    __shared__ float Kw[BK][64];
    __shared__ float Vw[BK][64];

    const int tid = threadIdx.x;
    const int tx = tid & 15;          // 0..15 -> 4 cols each
    const int ty = tid >> 4;          // 0..15 -> 4 rows each
    const int rowBase = blockIdx.y * 64;
    const int colBase = blockIdx.x * 64;
    const int lr = tid >> 2;          // 0..63
    const int lk = (tid & 3) << 2;    // 0,4,8,12

    float accQ[4][4] = {}, accK[4][4] = {}, accV[4][4] = {};

    const float* Fp = F  + (size_t)(rowBase + lr) * DDIM + lk;
    const float* Qp = Wq + (size_t)(colBase + lr) * DDIM + lk;
    const float* Kp = Wk + (size_t)(colBase + lr) * DDIM + lk;
    const float* Vp = Wv + (size_t)(colBase + lr) * DDIM + lk;

    for (int kb = 0; kb < DDIM; kb += BK) {
        float4 fa = *(const float4*)(Fp + kb);
        float4 qa = *(const float4*)(Qp + kb);
        float4 ka = *(const float4*)(Kp + kb);
        float4 va = *(const float4*)(Vp + kb);
        __syncthreads();
        Fs[lk+0][lr] = fa.x; Fs[lk+1][lr] = fa.y; Fs[lk+2][lr] = fa.z; Fs[lk+3][lr] = fa.w;
        Qw[lk+0][lr] = qa.x; Qw[lk+1][lr] = qa.y; Qw[lk+2][lr] = qa.z; Qw[lk+3][lr] = qa.w;
        Kw[lk+0][lr] = ka.x; Kw[lk+1][lr] = ka.y; Kw[lk+2][lr] = ka.z; Kw[lk+3][lr] = ka.w;
        Vw[lk+0][lr] = va.x; Vw[lk+1][lr] = va.y; Vw[lk+2][lr] = va.z; Vw[lk+3][lr] = va.w;
        __syncthreads();

        #pragma unroll
        for (int kk = 0; kk < BK; kk++) {
            float a[4], q[4], k2[4], v2[4];
            #pragma unroll
            for (int i = 0; i < 4; i++) a[i] = Fs[kk][ty*4 + i];
            #pragma unroll
            for (int j = 0; j < 4; j++) {
                q[j]  = Qw[kk][tx*4 + j];
                k2[j] = Kw[kk][tx*4 + j];
                v2[j] = Vw[kk][tx*4 + j];
            }
            #pragma unroll
            for (int i = 0; i < 4; i++)
                #pragma unroll
                for (int j = 0; j < 4; j++) {
                    accQ[i][j] = fmaf(a[i], q[j],  accQ[i][j]);
                    accK[i][j] = fmaf(a[i], k2[j], accK[i][j]);
                    accV[i][j] = fmaf(a[i], v2[j], accV[i][j]);
                }
        }
    }

    #pragma unroll
    for (int j = 0; j < 4; j++) {
        int c = colBase + tx*4 + j;
        float bqv = bq[c], bkv = bk[c], bvv = bv[c];
        #pragma unroll
        for (int i = 0; i < 4; i++) {
            int r = rowBase + ty*4 + i;
            g_Q[(size_t)r * DDIM + c] = accQ[i][j] + bqv;
            g_K[(size_t)r * DDIM + c] = accK[i][j] + bkv;
            g_V[(size_t)r * DDIM + c] = accV[i][j] + bvv;
        }
    }
}

// ============================================================
// Kernel 2: per-row squared norms of F
// ============================================================
__global__ void norm_kernel(const float* __restrict__ F)
{
    int row = blockIdx.x;
    const float4* fr = (const float4*)(F + (size_t)row * DDIM);
    float s = 0.f;
    for (int i = threadIdx.x; i < DDIM/4; i += blockDim.x) {
        float4 v = fr[i];
        s += v.x*v.x + v.y*v.y + v.z*v.z + v.w*v.w;
    }
    #pragma unroll
    for (int o = 16; o > 0; o >>= 1) s += __shfl_xor_sync(0xffffffffu, s, o);
    __shared__ float red[4];
    if ((threadIdx.x & 31) == 0) red[threadIdx.x >> 5] = s;
    __syncthreads();
    if (threadIdx.x == 0) g_norm[row] = red[0] + red[1] + red[2] + red[3];
}

// ============================================================
// Kernel 3: S = Q K^T and G = F F^T in one pass.
//   dist = sqrt(max(n_r + n_c - 2G, 0))  -> d_out dist region
//   T    = S / sqrt(D) - lam * dist      -> g_T
// 128x64 tile, 256 threads, 8x4 per thread, BK=16
// ============================================================
__global__ __launch_bounds__(256) void logits_dist_kernel(
    const float* __restrict__ F, const float* __restrict__ lamP,
    float* __restrict__ dist_out)
{
    const int BK = 16;
    __shared__ float Qs[BK][128];
    __shared__ float Fr[BK][128];
    __shared__ float Ks[BK][64];
    __shared__ float Fc[BK][64];

    const int tid = threadIdx.x;
    const int tx = tid & 15;          // 0..15 -> 4 cols
    const int ty = tid >> 4;          // 0..15 -> 8 rows
    const int rowBase = blockIdx.y * 128;
    const int colBase = blockIdx.x * 64;
    const int lr = tid >> 2;          // 0..63
    const int lk = (tid & 3) << 2;

    float accS[8][4] = {}, accG[8][4] = {};

    const float* Q0  = g_Q + (size_t)(rowBase + lr)      * DDIM + lk;
    const float* Q1  = g_Q + (size_t)(rowBase + 64 + lr) * DDIM + lk;
    const float* F0  = F   + (size_t)(rowBase + lr)      * DDIM + lk;
    const float* F1  = F   + (size_t)(rowBase + 64 + lr) * DDIM + lk;
    const float* K0  = g_K + (size_t)(colBase + lr)      * DDIM + lk;
    const float* Fc0 = F   + (size_t)(colBase + lr)      * DDIM + lk;

    for (int kb = 0; kb < DDIM; kb += BK) {
        float4 q0 = *(const float4*)(Q0 + kb);
        float4 q1 = *(const float4*)(Q1 + kb);
        float4 f0 = *(const float4*)(F0 + kb);
        float4 f1 = *(const float4*)(F1 + kb);
        float4 k4 = *(const float4*)(K0 + kb);
        float4 fc = *(const float4*)(Fc0 + kb);
        __syncthreads();
        Qs[lk+0][lr] = q0.x; Qs[lk+1][lr] = q0.y; Qs[lk+2][lr] = q0.z; Qs[lk+3][lr] = q0.w;
        Qs[lk+0][lr+64] = q1.x; Qs[lk+1][lr+64] = q1.y; Qs[lk+2][lr+64] = q1.z; Qs[lk+3][lr+64] = q1.w;
        Fr[lk+0][lr] = f0.x; Fr[lk+1][lr] = f0.y; Fr[lk+2][lr] = f0.z; Fr[lk+3][lr] = f0.w;
        Fr[lk+0][lr+64] = f1.x; Fr[lk+1][lr+64] = f1.y; Fr[lk+2][lr+64] = f1.z; Fr[lk+3][lr+64] = f1.w;
        Ks[lk+0][lr] = k4.x; Ks[lk+1][lr] = k4.y; Ks[lk+2][lr] = k4.z; Ks[lk+3][lr] = k4.w;
        Fc[lk+0][lr] = fc.x; Fc[lk+1][lr] = fc.y; Fc[lk+2][lr] = fc.z; Fc[lk+3][lr] = fc.w;
        __syncthreads();

        #pragma unroll
        for (int kk = 0; kk < BK; kk++) {
            float aQ[8], aF[8], bK[4], bF[4];
            #pragma unroll
            for (int i = 0; i < 8; i++) { aQ[i] = Qs[kk][ty*8 + i]; aF[i] = Fr[kk][ty*8 + i]; }
            #pragma unroll
            for (int j = 0; j < 4; j++) { bK[j] = Ks[kk][tx*4 + j]; bF[j] = Fc[kk][tx*4 + j]; }
            #pragma unroll
            for (int i = 0; i < 8; i++)
                #pragma unroll
                for (int j = 0; j < 4; j++) {
                    accS[i][j] = fmaf(aQ[i], bK[j], accS[i][j]);
                    accG[i][j] = fmaf(aF[i], bF[j], accG[i][j]);
                }
        }
    }

    const float lam = *lamP;
    const float inv_sqrt_d = 0.044194173824159216f;  // 1/sqrt(512)
    float ncol[4];
    #pragma unroll
    for (int j = 0; j < 4; j++) ncol[j] = g_norm[colBase + tx*4 + j];

    #pragma unroll
    for (int i = 0; i < 8; i++) {
        int r = rowBase + ty*8 + i;
        float nr = g_norm[r];
        #pragma unroll
        for (int j = 0; j < 4; j++) {
            int c = colBase + tx*4 + j;
            float sq = nr + ncol[j] - 2.f * accG[i][j];
            sq = fmaxf(sq, 0.f);
            float dd = sqrtf(sq);
            dist_out[(size_t)r * PP + c] = dd;
            g_T[(size_t)r * PP + c] = accS[i][j] * inv_sqrt_d - lam * dd;
        }
    }
}

// ============================================================
// Kernel 4: row softmax over g_T (in-place exp), store 1/sum
// ============================================================
__global__ __launch_bounds__(256) void softmax_kernel()
{
    int row = blockIdx.x;
    float* T = g_T + (size_t)row * PP;
    int tid = threadIdx.x;

    float m = -3.4e38f;
    for (int i = tid * 4; i < PP; i += 1024) {
        float4 v = *(const float4*)(T + i);
        m = fmaxf(m, fmaxf(fmaxf(v.x, v.y), fmaxf(v.z, v.w)));
    }
    __shared__ float red[8];
    #pragma unroll
    for (int o = 16; o > 0; o >>= 1) m = fmaxf(m, __shfl_xor_sync(0xffffffffu, m, o));
    if ((tid & 31) == 0) red[tid >> 5] = m;
    __syncthreads();
    if (tid == 0) {
        float bm = red[0];
        #pragma unroll
        for (int w = 1; w < 8; w++) bm = fmaxf(bm, red[w]);
        red[0] = bm;
    }
    __syncthreads();
    m = red[0];
    __syncthreads();

    float s = 0.f;
    for (int i = tid * 4; i < PP; i += 1024) {
        float4 v = *(float4*)(T + i);
        v.x = __expf(v.x - m);
        v.y = __expf(v.y - m);
        v.z = __expf(v.z - m);
        v.w = __expf(v.w - m);
        s += v.x + v.y + v.z + v.w;
        *(float4*)(T + i) = v;
    }
    #pragma unroll
    for (int o = 16; o > 0; o >>= 1) s += __shfl_xor_sync(0xffffffffu, s, o);
    if ((tid & 31) == 0) red[tid >> 5] = s;
    __syncthreads();
    if (tid == 0) {
        float bs = red[0];
        #pragma unroll
        for (int w = 1; w < 8; w++) bs += red[w];
        g_inv[row] = 1.f / bs;
    }
}

// ============================================================
// Kernel 5: F_out = (exp-probs @ V) * (1/sum) per row
// 128x128 tile, 256 threads, 8x8 per thread, BK=16
// ============================================================
__global__ __launch_bounds__(256) void av_kernel(float* __restrict__ out)
{
    const int BK = 16;
    __shared__ float As[BK][128];
    __shared__ float Bs[BK][128];

    const int tid = threadIdx.x;
    const int tx = tid & 15;          // 0..15 -> 8 cols
    const int ty = tid >> 4;          // 0..15 -> 8 rows
    const int rowBase = blockIdx.y * 128;
    const int colBase = blockIdx.x * 128;
    const int lr = tid >> 2;          // 0..63
    const int lk = (tid & 3) << 2;
    const int bk_k = tid >> 5;        // 0..7
    const int bk_c = (tid & 31) << 2; // 0..124

    float acc[8][8] = {};

    for (int kb = 0; kb < PP; kb += BK) {
        float4 a0 = *(const float4*)(g_T + (size_t)(rowBase + lr)      * PP + kb + lk);
        float4 a1 = *(const float4*)(g_T + (size_t)(rowBase + 64 + lr) * PP + kb + lk);
        float4 b0 = *(const float4*)(g_V + (size_t)(kb + bk_k)     * DDIM + colBase + bk_c);
        float4 b1 = *(const float4*)(g_V + (size_t)(kb + 8 + bk_k) * DDIM + colBase + bk_c);
        __syncthreads();
        As[lk+0][lr] = a0.x; As[lk+1][lr] = a0.y; As[lk+2][lr] = a0.z; As[lk+3][lr] = a0.w;
        As[lk+0][lr+64] = a1.x; As[lk+1][lr+64] = a1.y; As[lk+2][lr+64] = a1.z; As[lk+3][lr+64] = a1.w;
        *(float4*)&Bs[bk_k][bk_c]     = b0;
        *(float4*)&Bs[bk_k + 8][bk_c] = b1;
        __syncthreads();

        #pragma unroll
        for (int kk = 0; kk < BK; kk++) {
            float a[8], b[8];
            #pragma unroll
            for (int i = 0; i < 8; i++) a[i] = As[kk][ty*8 + i];
            #pragma unroll
            for (int j = 0; j < 8; j++) b[j] = Bs[kk][tx*8 + j];
            #pragma unroll
            for (int i = 0; i < 8; i++)
                #pragma unroll
                for (int j = 0; j < 8; j++)
                    acc[i][j] = fmaf(a[i], b[j], acc[i][j]);
        }
    }

    #pragma unroll
    for (int i = 0; i < 8; i++) {
        int r = rowBase + ty*8 + i;
        float inv = g_inv[r];
        #pragma unroll
        for (int j = 0; j < 8; j++) {
            out[(size_t)r * DDIM + colBase + tx*8 + j] = acc[i][j] * inv;
        }
    }
}

// ============================================================
extern "C" void kernel_launch(void* const* d_in, const int* in_sizes, int n_in,
                              void* d_out, int out_size)
{
    const float* F   = (const float*)d_in[0];
    const float* Wq  = (const float*)d_in[1];
    const float* bq  = (const float*)d_in[2];
    const float* Wk  = (const float*)d_in[3];
    const float* bk  = (const float*)d_in[4];
    const float* Wv  = (const float*)d_in[5];
    const float* bv  = (const float*)d_in[6];
    const float* lam = (const float*)d_in[7];

    float* out  = (float*)d_out;
    float* Fout = out;                        // [P, D]  first
    float* dist = out + (size_t)PP * DDIM;    // [P, P]  second

    qkv_kernel<<<dim3(DDIM/64, PP/64), 256>>>(F, Wq, bq, Wk, bk, Wv, bv);
    norm_kernel<<<PP, 128>>>(F);
    logits_dist_kernel<<<dim3(PP/64, PP/128), 256>>>(F, lam, dist);
    softmax_kernel<<<PP, 256>>>();
    av_kernel<<<dim3(DDIM/128, PP/128), 256>>>(Fout);
}

// round 2
// speedup vs baseline: 1.8538x; 1.8538x over previous
#include <cuda_runtime.h>
#include <math.h>
#include <stdint.h>

#define PP 8192
#define DDIM 512

// ---- scratch (device globals: allocation-free per harness rules) ----
__device__ float g_Q[PP * DDIM];
__device__ float g_K[PP * DDIM];
__device__ float g_V[PP * DDIM];
__device__ float g_norm[PP];
__device__ float g_inv[PP];
__device__ float g_T[(size_t)PP * PP];   // 256 MB: logits - lam*dist, then exp(...)

__device__ __forceinline__ float to_tf32(float x) {
    uint32_t u;
    asm("cvt.rna.tf32.f32 %0, %1;" : "=r"(u) : "f"(x));
    return __uint_as_float(u);
}

__device__ __forceinline__ void mma_tf32(float* d, const float* a, const float* b) {
    asm volatile(
        "mma.sync.aligned.m16n8k8.row.col.f32.tf32.tf32.f32 "
        "{%0,%1,%2,%3}, {%4,%5,%6,%7}, {%8,%9}, {%0,%1,%2,%3};"
        : "+f"(d[0]), "+f"(d[1]), "+f"(d[2]), "+f"(d[3])
        : "r"(__float_as_uint(a[0])), "r"(__float_as_uint(a[1])),
          "r"(__float_as_uint(a[2])), "r"(__float_as_uint(a[3])),
          "r"(__float_as_uint(b[0])), "r"(__float_as_uint(b[1])));
}

// ============================================================
// Kernel 1: Q/K/V = F @ W^T + b  (FFMA; only 13 GF)
// ============================================================
__global__ __launch_bounds__(256) void qkv_kernel(
    const float* __restrict__ F,
    const float* __restrict__ Wq, const float* __restrict__ bq,
    const float* __restrict__ Wk, const float* __restrict__ bk,
    const float* __restrict__ Wv, const float* __restrict__ bv)
{
    const int BK = 16;
    __shared__ float Fs[BK][64];
    __shared__ float Qw[BK][64];
    __shared__ float Kw[BK][64];
    __shared__ float Vw[BK][64];

    const int tid = threadIdx.x;
    const int tx = tid & 15;
    const int ty = tid >> 4;
    const int rowBase = blockIdx.y * 64;
    const int colBase = blockIdx.x * 64;
    const int lr = tid >> 2;
    const int lk = (tid & 3) << 2;

    float accQ[4][4] = {}, accK[4][4] = {}, accV[4][4] = {};

    const float* Fp = F  + (size_t)(rowBase + lr) * DDIM + lk;
    const float* Qp = Wq + (size_t)(colBase + lr) * DDIM + lk;
    const float* Kp = Wk + (size_t)(colBase + lr) * DDIM + lk;
    const float* Vp = Wv + (size_t)(colBase + lr) * DDIM + lk;

    for (int kb = 0; kb < DDIM; kb += BK) {
        float4 fa = *(const float4*)(Fp + kb);
        float4 qa = *(const float4*)(Qp + kb);
        float4 ka = *(const float4*)(Kp + kb);
        float4 va = *(const float4*)(Vp + kb);
        __syncthreads();
        Fs[lk+0][lr] = fa.x; Fs[lk+1][lr] = fa.y; Fs[lk+2][lr] = fa.z; Fs[lk+3][lr] = fa.w;
        Qw[lk+0][lr] = qa.x; Qw[lk+1][lr] = qa.y; Qw[lk+2][lr] = qa.z; Qw[lk+3][lr] = qa.w;
        Kw[lk+0][lr] = ka.x; Kw[lk+1][lr] = ka.y; Kw[lk+2][lr] = ka.z; Kw[lk+3][lr] = ka.w;
        Vw[lk+0][lr] = va.x; Vw[lk+1][lr] = va.y; Vw[lk+2][lr] = va.z; Vw[lk+3][lr] = va.w;
        __syncthreads();

        #pragma unroll
        for (int kk = 0; kk < BK; kk++) {
            float a[4], q[4], k2[4], v2[4];
            #pragma unroll
            for (int i = 0; i < 4; i++) a[i] = Fs[kk][ty*4 + i];
            #pragma unroll
            for (int j = 0; j < 4; j++) {
                q[j]  = Qw[kk][tx*4 + j];
                k2[j] = Kw[kk][tx*4 + j];
                v2[j] = Vw[kk][tx*4 + j];
            }
            #pragma unroll
            for (int i = 0; i < 4; i++)
                #pragma unroll
                for (int j = 0; j < 4; j++) {
                    accQ[i][j] = fmaf(a[i], q[j],  accQ[i][j]);
                    accK[i][j] = fmaf(a[i], k2[j], accK[i][j]);
                    accV[i][j] = fmaf(a[i], v2[j], accV[i][j]);
                }
        }
    }

    #pragma unroll
    for (int j = 0; j < 4; j++) {
        int c = colBase + tx*4 + j;
        float bqv = bq[c], bkv = bk[c], bvv = bv[c];
        #pragma unroll
        for (int i = 0; i < 4; i++) {
            int r = rowBase + ty*4 + i;
            g_Q[(size_t)r * DDIM + c] = accQ[i][j] + bqv;
            g_K[(size_t)r * DDIM + c] = accK[i][j] + bkv;
            g_V[(size_t)r * DDIM + c] = accV[i][j] + bvv;
        }
    }
}

// ============================================================
// Kernel 2: per-row squared norms of F
// ============================================================
__global__ void norm_kernel(const float* __restrict__ F)
{
    int row = blockIdx.x;
    const float4* fr = (const float4*)(F + (size_t)row * DDIM);
    float s = 0.f;
    for (int i = threadIdx.x; i < DDIM/4; i += blockDim.x) {
        float4 v = fr[i];
        s += v.x*v.x + v.y*v.y + v.z*v.z + v.w*v.w;
    }
    #pragma unroll
    for (int o = 16; o > 0; o >>= 1) s += __shfl_xor_sync(0xffffffffu, s, o);
    __shared__ float red[4];
    if ((threadIdx.x & 31) == 0) red[threadIdx.x >> 5] = s;
    __syncthreads();
    if (threadIdx.x == 0) g_norm[row] = red[0] + red[1] + red[2] + red[3];
}

// ============================================================
// Kernel 3 (tf32 MMA): S = Q K^T and G = F F^T in one k-loop.
//   dist = sqrt(max(n_r + n_c - 2G, 0))  -> dist output
//   T    = S / sqrt(D) - lam * dist      -> g_T
// Block tile 128x64, 8 warps (4x2), warp tile 32x32, BK=16.
// ============================================================
__global__ __launch_bounds__(256) void logits_dist_mma(
    const float* __restrict__ F, const float* __restrict__ lamP,
    float* __restrict__ dist_out)
{
    __shared__ float Qs[128][20];
    __shared__ float Fr[128][20];
    __shared__ float Ks[64][20];
    __shared__ float Fc[64][20];

    const int tid  = threadIdx.x;
    const int wid  = tid >> 5;
    const int lane = tid & 31;
    const int gr   = lane >> 2;       // 0..7
    const int tg   = lane & 3;        // 0..3
    const int warp_m = wid & 3;       // 0..3 -> 32-row slab
    const int warp_n = wid >> 2;      // 0..1 -> 32-col slab
    const int rowBase = blockIdx.y * 128;
    const int colBase = blockIdx.x * 64;

    // loader mapping
    const int lr  = tid >> 1;         // 0..127 (rows of Q/F)
    const int lk8 = (tid & 1) * 8;    // 0,8
    const int cr  = tid >> 2;         // 0..63 (rows of K/Fc)
    const int ck4 = (tid & 3) * 4;    // 0,4,8,12

    float accS[2][4][4] = {};
    float accG[2][4][4] = {};

    const float* Qg  = g_Q + (size_t)(rowBase + lr) * DDIM + lk8;
    const float* Fg  = F   + (size_t)(rowBase + lr) * DDIM + lk8;
    const float* Kg  = g_K + (size_t)(colBase + cr) * DDIM + ck4;
    const float* Fcg = F   + (size_t)(colBase + cr) * DDIM + ck4;

    for (int kb = 0; kb < DDIM; kb += 16) {
        float4 q0 = *(const float4*)(Qg + kb);
        float4 q1 = *(const float4*)(Qg + kb + 4);
        float4 f0 = *(const float4*)(Fg + kb);
        float4 f1 = *(const float4*)(Fg + kb + 4);
        float4 kv = *(const float4*)(Kg + kb);
        float4 cv = *(const float4*)(Fcg + kb);
        __syncthreads();
        Qs[lr][lk8+0] = to_tf32(q0.x); Qs[lr][lk8+1] = to_tf32(q0.y);
        Qs[lr][lk8+2] = to_tf32(q0.z); Qs[lr][lk8+3] = to_tf32(q0.w);
        Qs[lr][lk8+4] = to_tf32(q1.x); Qs[lr][lk8+5] = to_tf32(q1.y);
        Qs[lr][lk8+6] = to_tf32(q1.z); Qs[lr][lk8+7] = to_tf32(q1.w);
        Fr[lr][lk8+0] = to_tf32(f0.x); Fr[lr][lk8+1] = to_tf32(f0.y);
        Fr[lr][lk8+2] = to_tf32(f0.z); Fr[lr][lk8+3] = to_tf32(f0.w);
        Fr[lr][lk8+4] = to_tf32(f1.x); Fr[lr][lk8+5] = to_tf32(f1.y);
        Fr[lr][lk8+6] = to_tf32(f1.z); Fr[lr][lk8+7] = to_tf32(f1.w);
        Ks[cr][ck4+0] = to_tf32(kv.x); Ks[cr][ck4+1] = to_tf32(kv.y);
        Ks[cr][ck4+2] = to_tf32(kv.z); Ks[cr][ck4+3] = to_tf32(kv.w);
        Fc[cr][ck4+0] = to_tf32(cv.x); Fc[cr][ck4+1] = to_tf32(cv.y);
        Fc[cr][ck4+2] = to_tf32(cv.z); Fc[cr][ck4+3] = to_tf32(cv.w);
        __syncthreads();

        #pragma unroll
        for (int kk = 0; kk < 16; kk += 8) {
            float aQ[2][4], aF[2][4];
            #pragma unroll
            for (int tm = 0; tm < 2; tm++) {
                int r = warp_m*32 + tm*16 + gr;
                aQ[tm][0] = Qs[r][kk+tg];     aQ[tm][1] = Qs[r+8][kk+tg];
                aQ[tm][2] = Qs[r][kk+tg+4];   aQ[tm][3] = Qs[r+8][kk+tg+4];
                aF[tm][0] = Fr[r][kk+tg];     aF[tm][1] = Fr[r+8][kk+tg];
                aF[tm][2] = Fr[r][kk+tg+4];   aF[tm][3] = Fr[r+8][kk+tg+4];
            }
            float bK[4][2], bF[4][2];
            #pragma unroll
            for (int tn = 0; tn < 4; tn++) {
                int c = warp_n*32 + tn*8 + gr;
                bK[tn][0] = Ks[c][kk+tg];  bK[tn][1] = Ks[c][kk+tg+4];
                bF[tn][0] = Fc[c][kk+tg];  bF[tn][1] = Fc[c][kk+tg+4];
            }
            #pragma unroll
            for (int tm = 0; tm < 2; tm++)
                #pragma unroll
                for (int tn = 0; tn < 4; tn++) {
                    mma_tf32(accS[tm][tn], aQ[tm], bK[tn]);
                    mma_tf32(accG[tm][tn], aF[tm], bF[tn]);
                }
        }
    }

    const float lam = *lamP;
    const float isd = 0.044194173824159216f;  // 1/sqrt(512)

    #pragma unroll
    for (int tm = 0; tm < 2; tm++) {
        int r0 = rowBase + warp_m*32 + tm*16 + gr;
        int r1 = r0 + 8;
        float n0 = g_norm[r0], n1 = g_norm[r1];
        #pragma unroll
        for (int tn = 0; tn < 4; tn++) {
            int c = colBase + warp_n*32 + tn*8 + 2*tg;
            float nc0 = g_norm[c], nc1 = g_norm[c+1];
            float* S = accS[tm][tn];
            float* G = accG[tm][tn];
            float d00 = sqrtf(fmaxf(n0 + nc0 - 2.f*G[0], 0.f));
            float d01 = sqrtf(fmaxf(n0 + nc1 - 2.f*G[1], 0.f));
            float d10 = sqrtf(fmaxf(n1 + nc0 - 2.f*G[2], 0.f));
            float d11 = sqrtf(fmaxf(n1 + nc1 - 2.f*G[3], 0.f));
            size_t o0 = (size_t)r0 * PP + c;
            size_t o1 = (size_t)r1 * PP + c;
            float2 dd0 = {d00, d01};
            float2 dd1 = {d10, d11};
            *(float2*)(dist_out + o0) = dd0;
            *(float2*)(dist_out + o1) = dd1;
            float2 t0 = {S[0]*isd - lam*d00, S[1]*isd - lam*d01};
            float2 t1 = {S[2]*isd - lam*d10, S[3]*isd - lam*d11};
            *(float2*)(g_T + o0) = t0;
            *(float2*)(g_T + o1) = t1;
        }
    }
}

// ============================================================
// Kernel 4: row softmax over g_T (in-place exp), store 1/sum
// ============================================================
__global__ __launch_bounds__(256) void softmax_kernel()
{
    int row = blockIdx.x;
    float* T = g_T + (size_t)row * PP;
    int tid = threadIdx.x;

    float m = -3.4e38f;
    for (int i = tid * 4; i < PP; i += 1024) {
        float4 v = *(const float4*)(T + i);
        m = fmaxf(m, fmaxf(fmaxf(v.x, v.y), fmaxf(v.z, v.w)));
    }
    __shared__ float red[8];
    #pragma unroll
    for (int o = 16; o > 0; o >>= 1) m = fmaxf(m, __shfl_xor_sync(0xffffffffu, m, o));
    if ((tid & 31) == 0) red[tid >> 5] = m;
    __syncthreads();
    if (tid == 0) {
        float bm = red[0];
        #pragma unroll
        for (int w = 1; w < 8; w++) bm = fmaxf(bm, red[w]);
        red[0] = bm;
    }
    __syncthreads();
    m = red[0];
    __syncthreads();

    float s = 0.f;
    for (int i = tid * 4; i < PP; i += 1024) {
        float4 v = *(float4*)(T + i);
        v.x = __expf(v.x - m);
        v.y = __expf(v.y - m);
        v.z = __expf(v.z - m);
        v.w = __expf(v.w - m);
        s += v.x + v.y + v.z + v.w;
        *(float4*)(T + i) = v;
    }
    #pragma unroll
    for (int o = 16; o > 0; o >>= 1) s += __shfl_xor_sync(0xffffffffu, s, o);
    if ((tid & 31) == 0) red[tid >> 5] = s;
    __syncthreads();
    if (tid == 0) {
        float bs = red[0];
        #pragma unroll
        for (int w = 1; w < 8; w++) bs += red[w];
        g_inv[row] = 1.f / bs;
    }
}

// ============================================================
// Kernel 5 (tf32 MMA): F_out = (exp-probs @ V) * (1/sum)
// Block tile 128x64, 8 warps (4x2), warp tile 32x32, BK=32.
// ============================================================
__global__ __launch_bounds__(256) void av_mma(float* __restrict__ out)
{
    __shared__ float As[128][36];
    __shared__ float Vs[32][72];

    const int tid  = threadIdx.x;
    const int wid  = tid >> 5;
    const int lane = tid & 31;
    const int gr   = lane >> 2;
    const int tg   = lane & 3;
    const int warp_m = wid & 3;
    const int warp_n = wid >> 2;
    const int rowBase = blockIdx.y * 128;
    const int colBase = blockIdx.x * 64;

    const int lr   = tid >> 1;          // 0..127
    const int lk16 = (tid & 1) * 16;    // 0,16
    const int vr   = tid >> 3;          // 0..31
    const int vc   = (tid & 7) * 8;     // 0..56

    float acc[2][4][4] = {};

    const float* Ag = g_T + (size_t)(rowBase + lr) * PP + lk16;
    const float* Vg = g_V + (size_t)vr * DDIM + colBase + vc;

    for (int kb = 0; kb < PP; kb += 32) {
        float4 a0 = *(const float4*)(Ag + kb);
        float4 a1 = *(const float4*)(Ag + kb + 4);
        float4 a2 = *(const float4*)(Ag + kb + 8);
        float4 a3 = *(const float4*)(Ag + kb + 12);
        float4 v0 = *(const float4*)(Vg + (size_t)kb * DDIM);
        float4 v1 = *(const float4*)(Vg + (size_t)kb * DDIM + 4);
        __syncthreads();
        As[lr][lk16+0]  = to_tf32(a0.x); As[lr][lk16+1]  = to_tf32(a0.y);
        As[lr][lk16+2]  = to_tf32(a0.z); As[lr][lk16+3]  = to_tf32(a0.w);
        As[lr][lk16+4]  = to_tf32(a1.x); As[lr][lk16+5]  = to_tf32(a1.y);
        As[lr][lk16+6]  = to_tf32(a1.z); As[lr][lk16+7]  = to_tf32(a1.w);
        As[lr][lk16+8]  = to_tf32(a2.x); As[lr][lk16+9]  = to_tf32(a2.y);
        As[lr][lk16+10] = to_tf32(a2.z); As[lr][lk16+11] = to_tf32(a2.w);
        As[lr][lk16+12] = to_tf32(a3.x); As[lr][lk16+13] = to_tf32(a3.y);
        As[lr][lk16+14] = to_tf32(a3.z); As[lr][lk16+15] = to_tf32(a3.w);
        Vs[vr][vc+0] = to_tf32(v0.x); Vs[vr][vc+1] = to_tf32(v0.y);
        Vs[vr][vc+2] = to_tf32(v0.z); Vs[vr][vc+3] = to_tf32(v0.w);
        Vs[vr][vc+4] = to_tf32(v1.x); Vs[vr][vc+5] = to_tf32(v1.y);
        Vs[vr][vc+6] = to_tf32(v1.z); Vs[vr][vc+7] = to_tf32(v1.w);
        __syncthreads();

        #pragma unroll
        for (int kk = 0; kk < 32; kk += 8) {
            float a[2][4];
            #pragma unroll
            for (int tm = 0; tm < 2; tm++) {
                int r = warp_m*32 + tm*16 + gr;
                a[tm][0] = As[r][kk+tg];   a[tm][1] = As[r+8][kk+tg];
                a[tm][2] = As[r][kk+tg+4]; a[tm][3] = As[r+8][kk+tg+4];
            }
            float b[4][2];
            #pragma unroll
            for (int tn = 0; tn < 4; tn++) {
                int c = warp_n*32 + tn*8 + gr;
                b[tn][0] = Vs[kk+tg][c];
                b[tn][1] = Vs[kk+tg+4][c];
            }
            #pragma unroll
            for (int tm = 0; tm < 2; tm++)
                #pragma unroll
                for (int tn = 0; tn < 4; tn++)
                    mma_tf32(acc[tm][tn], a[tm], b[tn]);
        }
    }

    #pragma unroll
    for (int tm = 0; tm < 2; tm++) {
        int r0 = rowBase + warp_m*32 + tm*16 + gr;
        int r1 = r0 + 8;
        float i0 = g_inv[r0], i1 = g_inv[r1];
        #pragma unroll
        for (int tn = 0; tn < 4; tn++) {
            int c = colBase + warp_n*32 + tn*8 + 2*tg;
            float* A = acc[tm][tn];
            float2 o0 = {A[0]*i0, A[1]*i0};
            float2 o1 = {A[2]*i1, A[3]*i1};
            *(float2*)(out + (size_t)r0 * DDIM + c) = o0;
            *(float2*)(out + (size_t)r1 * DDIM + c) = o1;
        }
    }
}

// ============================================================
extern "C" void kernel_launch(void* const* d_in, const int* in_sizes, int n_in,
                              void* d_out, int out_size)
{
    const float* F   = (const float*)d_in[0];
    const float* Wq  = (const float*)d_in[1];
    const float* bq  = (const float*)d_in[2];
    const float* Wk  = (const float*)d_in[3];
    const float* bk  = (const float*)d_in[4];
    const float* Wv  = (const float*)d_in[5];
    const float* bv  = (const float*)d_in[6];
    const float* lam = (const float*)d_in[7];

    float* out  = (float*)d_out;
    float* Fout = out;                        // [P, D]  first
    float* dist = out + (size_t)PP * DDIM;    // [P, P]  second

    qkv_kernel<<<dim3(DDIM/64, PP/64), 256>>>(F, Wq, bq, Wk, bk, Wv, bv);
    norm_kernel<<<PP, 128>>>(F);
    logits_dist_mma<<<dim3(PP/64, PP/128), 256>>>(F, lam, dist);
    softmax_kernel<<<PP, 256>>>();
    av_mma<<<dim3(DDIM/64, PP/128), 256>>>(Fout);
}

// round 4
// speedup vs baseline: 2.4170x; 1.3038x over previous
#include <cuda_runtime.h>
#include <math.h>
#include <stdint.h>

#define PP 8192
#define DDIM 512

// ---- scratch (device globals) ----
__device__ float g_Q[PP * DDIM];
__device__ float g_K[PP * DDIM];
__device__ float g_Vt[DDIM * PP];        // V transposed: [feature][position]
__device__ float g_norm[PP];
__device__ float g_inv[PP];
__device__ float g_T[(size_t)PP * PP];   // 256 MB

// ---------------- helpers ----------------
__device__ __forceinline__ float to_tf32(float x) {
    uint32_t u; asm("cvt.rna.tf32.f32 %0, %1;" : "=r"(u) : "f"(x));
    return __uint_as_float(u);
}
__device__ __forceinline__ float4 cvt4(float4 v) {
    v.x = to_tf32(v.x); v.y = to_tf32(v.y); v.z = to_tf32(v.z); v.w = to_tf32(v.w);
    return v;
}
__device__ __forceinline__ void mma8(float* d, const uint32_t* a, const uint32_t* b) {
    asm volatile(
        "mma.sync.aligned.m16n8k8.row.col.f32.tf32.tf32.f32 "
        "{%0,%1,%2,%3},{%4,%5,%6,%7},{%8,%9},{%0,%1,%2,%3};"
        : "+f"(d[0]), "+f"(d[1]), "+f"(d[2]), "+f"(d[3])
        : "r"(a[0]), "r"(a[1]), "r"(a[2]), "r"(a[3]), "r"(b[0]), "r"(b[1]));
}
__device__ __forceinline__ void ldsm4(uint32_t addr, uint32_t* r) {
    asm volatile("ldmatrix.sync.aligned.m8n8.x4.shared.b16 {%0,%1,%2,%3}, [%4];"
        : "=r"(r[0]), "=r"(r[1]), "=r"(r[2]), "=r"(r[3]) : "r"(addr));
}
// tile rows of 16 floats (64B), 16B chunks XOR-swizzled
__device__ __forceinline__ int sw_off(int r, int c) {
    return r * 64 + ((c ^ ((r >> 1) & 3)) << 4);
}
__device__ __forceinline__ uint32_t s2u(const void* p) {
    return (uint32_t)__cvta_generic_to_shared(p);
}

struct F4x2 { float4 a, b; };
// 128-row x 16-col tile loaders: 256 threads, 2 float4 each
__device__ __forceinline__ F4x2 ldgA(const float* base, int ld, int kb, int tid) {
    int r = tid >> 1, c0 = (tid & 1) * 2;
    const float* p = base + (size_t)r * ld + kb + c0 * 4;
    F4x2 s; s.a = *(const float4*)p; s.b = *(const float4*)(p + 4);
    return s;
}
__device__ __forceinline__ void stsA(char* tile, F4x2 s, int tid) {
    int r = tid >> 1, c0 = (tid & 1) * 2;
    *(float4*)(tile + sw_off(r, c0))     = cvt4(s.a);
    *(float4*)(tile + sw_off(r, c0 + 1)) = cvt4(s.b);
}
// 64-row x 16-col tile loaders: 256 threads, 1 float4 each
__device__ __forceinline__ float4 ldgB64(const float* base, int ld, int kb, int tid) {
    int r = tid >> 2, c = tid & 3;
    return *(const float4*)(base + (size_t)r * ld + kb + c * 4);
}
__device__ __forceinline__ void stsB64(char* tile, float4 v, int tid) {
    int r = tid >> 2, c = tid & 3;
    *(float4*)(tile + sw_off(r, c)) = cvt4(v);
}
// a-frag for m16 tile rows R..R+15, k8-step ks -> 4 regs
__device__ __forceinline__ void fragA(uint32_t tbase, int R, int ks, int lane, uint32_t* a) {
    int mi = lane >> 3, ri = lane & 7;
    int r = R + ri + (mi & 1) * 8;
    int c = ks * 2 + (mi >> 1);
    ldsm4(tbase + sw_off(r, c), a);
}
// b-frags for TWO n8 tiles (rows N0..N0+15), k8-step ks -> 4 regs: [b0_t0,b1_t0,b0_t1,b1_t1]
__device__ __forceinline__ void fragB(uint32_t tbase, int N0, int ks, int lane, uint32_t* b) {
    int mi = lane >> 3, ri = lane & 7;
    int r = N0 + ri + (mi >> 1) * 8;
    int c = ks * 2 + (mi & 1);
    ldsm4(tbase + sw_off(r, c), b);
}

// ============================================================
// Kernel 1: Q/K/V projections, tf32 MMA. Block 128x64, warp 32x32.
// V written transposed into g_Vt.
// ============================================================
__global__ __launch_bounds__(256) void qkv_mma(
    const float* __restrict__ F,
    const float* __restrict__ Wq, const float* __restrict__ bq,
    const float* __restrict__ Wk, const float* __restrict__ bk,
    const float* __restrict__ Wv, const float* __restrict__ bv)
{
    __shared__ char smem[2 * 20 * 1024];
    const int tid = threadIdx.x, lane = tid & 31, wid = tid >> 5;
    const int wm = wid & 3, wn = wid >> 2;
    const int rowBase = blockIdx.y * 128, colBase = blockIdx.x * 64;

    float aq[2][4][4] = {}, ak[2][4][4] = {}, avv[2][4][4] = {};

    const float* Fb = F  + (size_t)rowBase * DDIM;
    const float* Qb = Wq + (size_t)colBase * DDIM;
    const float* Kb = Wk + (size_t)colBase * DDIM;
    const float* Vb = Wv + (size_t)colBase * DDIM;

    F4x2  sA = ldgA(Fb, DDIM, 0, tid);
    float4 sQ = ldgB64(Qb, DDIM, 0, tid);
    float4 sK = ldgB64(Kb, DDIM, 0, tid);
    float4 sV = ldgB64(Vb, DDIM, 0, tid);
    char* buf0 = smem; char* buf1 = smem + 20 * 1024;
    stsA(buf0, sA, tid);
    stsB64(buf0 +  8192, sQ, tid);
    stsB64(buf0 + 12288, sK, tid);
    stsB64(buf0 + 16384, sV, tid);
    __syncthreads();

    const int NKB = DDIM / 16;
    for (int kb = 0; kb < NKB; kb++) {
        if (kb + 1 < NKB) {
            int k = (kb + 1) * 16;
            sA = ldgA(Fb, DDIM, k, tid);
            sQ = ldgB64(Qb, DDIM, k, tid);
            sK = ldgB64(Kb, DDIM, k, tid);
            sV = ldgB64(Vb, DDIM, k, tid);
        }
        char* cur = (kb & 1) ? buf1 : buf0;
        uint32_t su = s2u(cur);
        #pragma unroll
        for (int ks = 0; ks < 2; ks++) {
            uint32_t a[2][4];
            fragA(su, wm * 32,      ks, lane, a[0]);
            fragA(su, wm * 32 + 16, ks, lane, a[1]);
            #pragma unroll
            for (int p = 0; p < 2; p++) {
                uint32_t b[4];
                fragB(su + 8192, wn * 32 + p * 16, ks, lane, b);
                #pragma unroll
                for (int tm = 0; tm < 2; tm++) {
                    mma8(aq[tm][2*p],   a[tm], b);
                    mma8(aq[tm][2*p+1], a[tm], b + 2);
                }
                fragB(su + 12288, wn * 32 + p * 16, ks, lane, b);
                #pragma unroll
                for (int tm = 0; tm < 2; tm++) {
                    mma8(ak[tm][2*p],   a[tm], b);
                    mma8(ak[tm][2*p+1], a[tm], b + 2);
                }
                fragB(su + 16384, wn * 32 + p * 16, ks, lane, b);
                #pragma unroll
                for (int tm = 0; tm < 2; tm++) {
                    mma8(avv[tm][2*p],   a[tm], b);
                    mma8(avv[tm][2*p+1], a[tm], b + 2);
                }
            }
        }
        char* nxt = (kb & 1) ? buf0 : buf1;
        if (kb + 1 < NKB) {
            stsA(nxt, sA, tid);
            stsB64(nxt +  8192, sQ, tid);
            stsB64(nxt + 12288, sK, tid);
            stsB64(nxt + 16384, sV, tid);
        }
        __syncthreads();
    }

    const int gr = lane >> 2, tg = lane & 3;
    #pragma unroll
    for (int tm = 0; tm < 2; tm++) {
        int r0 = rowBase + wm * 32 + tm * 16 + gr, r1 = r0 + 8;
        #pragma unroll
        for (int tn = 0; tn < 4; tn++) {
            int c = colBase + wn * 32 + tn * 8 + 2 * tg;
            float bq0 = bq[c], bq1 = bq[c+1];
            float bk0 = bk[c], bk1 = bk[c+1];
            float bv0 = bv[c], bv1 = bv[c+1];
            float* A = aq[tm][tn];
            *(float2*)(g_Q + (size_t)r0 * DDIM + c) = make_float2(A[0] + bq0, A[1] + bq1);
            *(float2*)(g_Q + (size_t)r1 * DDIM + c) = make_float2(A[2] + bq0, A[3] + bq1);
            A = ak[tm][tn];
            *(float2*)(g_K + (size_t)r0 * DDIM + c) = make_float2(A[0] + bk0, A[1] + bk1);
            *(float2*)(g_K + (size_t)r1 * DDIM + c) = make_float2(A[2] + bk0, A[3] + bk1);
            A = avv[tm][tn];
            g_Vt[(size_t)c     * PP + r0] = A[0] + bv0;
            g_Vt[(size_t)(c+1) * PP + r0] = A[1] + bv1;
            g_Vt[(size_t)c     * PP + r1] = A[2] + bv0;
            g_Vt[(size_t)(c+1) * PP + r1] = A[3] + bv1;
        }
    }
}

// ============================================================
// Kernel 2: per-row squared norms of F
// ============================================================
__global__ void norm_kernel(const float* __restrict__ F)
{
    int row = blockIdx.x;
    const float4* fr = (const float4*)(F + (size_t)row * DDIM);
    float s = 0.f;
    for (int i = threadIdx.x; i < DDIM / 4; i += blockDim.x) {
        float4 v = fr[i];
        s += v.x*v.x + v.y*v.y + v.z*v.z + v.w*v.w;
    }
    #pragma unroll
    for (int o = 16; o > 0; o >>= 1) s += __shfl_xor_sync(0xffffffffu, s, o);
    __shared__ float red[4];
    if ((threadIdx.x & 31) == 0) red[threadIdx.x >> 5] = s;
    __syncthreads();
    if (threadIdx.x == 0) g_norm[row] = red[0] + red[1] + red[2] + red[3];
}

// ============================================================
// Kernel 3: S=QK^T and G=FF^T fused, tf32 MMA + ldmatrix.
// Block 128x128, 8 warps (4m x 2n), warp 32x64. Dynamic smem 64KB.
// ============================================================
__global__ __launch_bounds__(256) void logits_mma(
    const float* __restrict__ F, const float* __restrict__ lamP,
    float* __restrict__ dist_out)
{
    extern __shared__ char dsm[];
    const int tid = threadIdx.x, lane = tid & 31, wid = tid >> 5;
    const int wm = wid & 3, wn = wid >> 2;
    const int rowBase = blockIdx.y * 128, colBase = blockIdx.x * 128;

    float accS[2][8][4] = {}, accG[2][8][4] = {};

    const float* Qb = g_Q + (size_t)rowBase * DDIM;
    const float* Fr = F   + (size_t)rowBase * DDIM;
    const float* Kb = g_K + (size_t)colBase * DDIM;
    const float* Cb = F   + (size_t)colBase * DDIM;

    F4x2 s0 = ldgA(Qb, DDIM, 0, tid);
    F4x2 s1 = ldgA(Fr, DDIM, 0, tid);
    F4x2 s2 = ldgA(Kb, DDIM, 0, tid);
    F4x2 s3 = ldgA(Cb, DDIM, 0, tid);
    stsA(dsm,         s0, tid);
    stsA(dsm +  8192, s1, tid);
    stsA(dsm + 16384, s2, tid);
    stsA(dsm + 24576, s3, tid);
    __syncthreads();

    const int NKB = DDIM / 16;
    for (int kb = 0; kb < NKB; kb++) {
        if (kb + 1 < NKB) {
            int k = (kb + 1) * 16;
            s0 = ldgA(Qb, DDIM, k, tid);
            s1 = ldgA(Fr, DDIM, k, tid);
            s2 = ldgA(Kb, DDIM, k, tid);
            s3 = ldgA(Cb, DDIM, k, tid);
        }
        uint32_t su = s2u(dsm + (kb & 1) * 32768);
        #pragma unroll
        for (int ks = 0; ks < 2; ks++) {
            {   // S = Q K^T
                uint32_t a[2][4];
                fragA(su, wm * 32,      ks, lane, a[0]);
                fragA(su, wm * 32 + 16, ks, lane, a[1]);
                #pragma unroll
                for (int p = 0; p < 4; p++) {
                    uint32_t b[4];
                    fragB(su + 16384, wn * 64 + p * 16, ks, lane, b);
                    #pragma unroll
                    for (int tm = 0; tm < 2; tm++) {
                        mma8(accS[tm][2*p],   a[tm], b);
                        mma8(accS[tm][2*p+1], a[tm], b + 2);
                    }
                }
            }
            {   // G = F F^T
                uint32_t a[2][4];
                fragA(su + 8192, wm * 32,      ks, lane, a[0]);
                fragA(su + 8192, wm * 32 + 16, ks, lane, a[1]);
                #pragma unroll
                for (int p = 0; p < 4; p++) {
                    uint32_t b[4];
                    fragB(su + 24576, wn * 64 + p * 16, ks, lane, b);
                    #pragma unroll
                    for (int tm = 0; tm < 2; tm++) {
                        mma8(accG[tm][2*p],   a[tm], b);
                        mma8(accG[tm][2*p+1], a[tm], b + 2);
                    }
                }
            }
        }
        char* nxt = dsm + ((kb + 1) & 1) * 32768;
        if (kb + 1 < NKB) {
            stsA(nxt,         s0, tid);
            stsA(nxt +  8192, s1, tid);
            stsA(nxt + 16384, s2, tid);
            stsA(nxt + 24576, s3, tid);
        }
        __syncthreads();
    }

    const int gr = lane >> 2, tg = lane & 3;
    const float lam = *lamP;
    const float isd = 0.044194173824159216f;  // 1/sqrt(512)
    #pragma unroll
    for (int tm = 0; tm < 2; tm++) {
        int r0 = rowBase + wm * 32 + tm * 16 + gr, r1 = r0 + 8;
        float n0 = g_norm[r0], n1 = g_norm[r1];
        #pragma unroll
        for (int tn = 0; tn < 8; tn++) {
            int c = colBase + wn * 64 + tn * 8 + 2 * tg;
            float nc0 = g_norm[c], nc1 = g_norm[c+1];
            float* S = accS[tm][tn];
            float* G = accG[tm][tn];
            float d00 = sqrtf(fmaxf(n0 + nc0 - 2.f * G[0], 0.f));
            float d01 = sqrtf(fmaxf(n0 + nc1 - 2.f * G[1], 0.f));
            float d10 = sqrtf(fmaxf(n1 + nc0 - 2.f * G[2], 0.f));
            float d11 = sqrtf(fmaxf(n1 + nc1 - 2.f * G[3], 0.f));
            size_t o0 = (size_t)r0 * PP + c, o1 = (size_t)r1 * PP + c;
            *(float2*)(dist_out + o0) = make_float2(d00, d01);
            *(float2*)(dist_out + o1) = make_float2(d10, d11);
            *(float2*)(g_T + o0) = make_float2(S[0]*isd - lam*d00, S[1]*isd - lam*d01);
            *(float2*)(g_T + o1) = make_float2(S[2]*isd - lam*d10, S[3]*isd - lam*d11);
        }
    }
}

// ============================================================
// Kernel 4: row softmax over g_T (in-place exp), store 1/sum
// ============================================================
__global__ __launch_bounds__(256) void softmax_kernel()
{
    int row = blockIdx.x;
    float* T = g_T + (size_t)row * PP;
    int tid = threadIdx.x;

    float m = -3.4e38f;
    for (int i = tid * 4; i < PP; i += 1024) {
        float4 v = *(const float4*)(T + i);
        m = fmaxf(m, fmaxf(fmaxf(v.x, v.y), fmaxf(v.z, v.w)));
    }
    __shared__ float red[8];
    #pragma unroll
    for (int o = 16; o > 0; o >>= 1) m = fmaxf(m, __shfl_xor_sync(0xffffffffu, m, o));
    if ((tid & 31) == 0) red[tid >> 5] = m;
    __syncthreads();
    if (tid == 0) {
        float bm = red[0];
        #pragma unroll
        for (int w = 1; w < 8; w++) bm = fmaxf(bm, red[w]);
        red[0] = bm;
    }
    __syncthreads();
    m = red[0];
    __syncthreads();

    float s = 0.f;
    for (int i = tid * 4; i < PP; i += 1024) {
        float4 v = *(float4*)(T + i);
        v.x = __expf(v.x - m);
        v.y = __expf(v.y - m);
        v.z = __expf(v.z - m);
        v.w = __expf(v.w - m);
        s += v.x + v.y + v.z + v.w;
        *(float4*)(T + i) = v;
    }
    #pragma unroll
    for (int o = 16; o > 0; o >>= 1) s += __shfl_xor_sync(0xffffffffu, s, o);
    if ((tid & 31) == 0) red[tid >> 5] = s;
    __syncthreads();
    if (tid == 0) {
        float bs = red[0];
        #pragma unroll
        for (int w = 1; w < 8; w++) bs += red[w];
        g_inv[row] = 1.f / bs;
    }
}

// ============================================================
// Kernel 5: F_out = (probs @ V) * (1/sum). tf32 MMA + ldmatrix.
// Block 128x128 (rows x features), warp 32x64. B = g_Vt (K-major).
// ============================================================
__global__ __launch_bounds__(256) void av_mma(float* __restrict__ out)
{
    __shared__ char smem[2 * 16 * 1024];
    const int tid = threadIdx.x, lane = tid & 31, wid = tid >> 5;
    const int wm = wid & 3, wn = wid >> 2;
    const int rowBase = blockIdx.y * 128, colBase = blockIdx.x * 128;

    float acc[2][8][4] = {};

    const float* Ab = g_T  + (size_t)rowBase * PP;
    const float* Bb = g_Vt + (size_t)colBase * PP;

    F4x2 s0 = ldgA(Ab, PP, 0, tid);
    F4x2 s1 = ldgA(Bb, PP, 0, tid);
    char* buf0 = smem; char* buf1 = smem + 16 * 1024;
    stsA(buf0,        s0, tid);
    stsA(buf0 + 8192, s1, tid);
    __syncthreads();

    const int NKB = PP / 16;
    for (int kb = 0; kb < NKB; kb++) {
        if (kb + 1 < NKB) {
            int k = (kb + 1) * 16;
            s0 = ldgA(Ab, PP, k, tid);
            s1 = ldgA(Bb, PP, k, tid);
        }
        uint32_t su = s2u((kb & 1) ? buf1 : buf0);
        #pragma unroll
        for (int ks = 0; ks < 2; ks++) {
            uint32_t a[2][4];
            fragA(su, wm * 32,      ks, lane, a[0]);
            fragA(su, wm * 32 + 16, ks, lane, a[1]);
            #pragma unroll
            for (int p = 0; p < 4; p++) {
                uint32_t b[4];
                fragB(su + 8192, wn * 64 + p * 16, ks, lane, b);
                #pragma unroll
                for (int tm = 0; tm < 2; tm++) {
                    mma8(acc[tm][2*p],   a[tm], b);
                    mma8(acc[tm][2*p+1], a[tm], b + 2);
                }
            }
        }
        char* nxt = (kb & 1) ? buf0 : buf1;
        if (kb + 1 < NKB) {
            stsA(nxt,        s0, tid);
            stsA(nxt + 8192, s1, tid);
        }
        __syncthreads();
    }

    const int gr = lane >> 2, tg = lane & 3;
    #pragma unroll
    for (int tm = 0; tm < 2; tm++) {
        int r0 = rowBase + wm * 32 + tm * 16 + gr, r1 = r0 + 8;
        float i0 = g_inv[r0], i1 = g_inv[r1];
        #pragma unroll
        for (int tn = 0; tn < 8; tn++) {
            int c = colBase + wn * 64 + tn * 8 + 2 * tg;
            float* A = acc[tm][tn];
            *(float2*)(out + (size_t)r0 * DDIM + c) = make_float2(A[0]*i0, A[1]*i0);
            *(float2*)(out + (size_t)r1 * DDIM + c) = make_float2(A[2]*i1, A[3]*i1);
        }
    }
}

// ============================================================
extern "C" void kernel_launch(void* const* d_in, const int* in_sizes, int n_in,
                              void* d_out, int out_size)
{
    const float* F   = (const float*)d_in[0];
    const float* Wq  = (const float*)d_in[1];
    const float* bq  = (const float*)d_in[2];
    const float* Wk  = (const float*)d_in[3];
    const float* bk  = (const float*)d_in[4];
    const float* Wv  = (const float*)d_in[5];
    const float* bv  = (const float*)d_in[6];
    const float* lam = (const float*)d_in[7];

    float* out  = (float*)d_out;
    float* Fout = out;                        // [P, D]
    float* dist = out + (size_t)PP * DDIM;    // [P, P]

    cudaFuncSetAttribute(logits_mma, cudaFuncAttributeMaxDynamicSharedMemorySize, 65536);

    qkv_mma<<<dim3(DDIM/64, PP/128), 256>>>(F, Wq, bq, Wk, bk, Wv, bv);
    norm_kernel<<<PP, 128>>>(F);
    logits_mma<<<dim3(PP/128, PP/128), 256, 65536>>>(F, lam, dist);
    softmax_kernel<<<PP, 256>>>();
    av_mma<<<dim3(DDIM/128, PP/128), 256>>>(Fout);
}

// round 7
// speedup vs baseline: 4.6996x; 1.9444x over previous
#include <cuda_runtime.h>
#include <cuda_fp16.h>
#include <math.h>
#include <stdint.h>

#define PP 8192
#define DDIM 512

// ---- scratch (device globals) ----
__device__ __half g_Qh[PP * DDIM];
__device__ __half g_Kh[PP * DDIM];
__device__ __half g_Fh[PP * DDIM];
__device__ __half g_Vth[DDIM * PP];          // V transposed: [feature][position]
__device__ __half g_Th[(size_t)PP * PP];     // exp probs (fp16), 128 MB
__device__ float  g_T[(size_t)PP * PP];      // logits - lam*dist (fp32), 256 MB
__device__ float  g_norm[PP];
__device__ float  g_inv[PP];

// ---------------- helpers ----------------
__device__ __forceinline__ uint32_t s2u(const void* p) {
    return (uint32_t)__cvta_generic_to_shared(p);
}
__device__ __forceinline__ uint32_t f2h2(float a, float b) {
    __half2 h = __floats2half2_rn(a, b);
    return *reinterpret_cast<uint32_t*>(&h);
}
// tile rows of 32 halves (64B), 16B chunks XOR-swizzled
__device__ __forceinline__ int swz64(int r, int c) {
    return r * 64 + ((c ^ ((r >> 1) & 3)) << 4);
}
__device__ __forceinline__ void mma16(float* d, const uint32_t* a, const uint32_t* b) {
    asm volatile(
        "mma.sync.aligned.m16n8k16.row.col.f32.f16.f16.f32 "
        "{%0,%1,%2,%3},{%4,%5,%6,%7},{%8,%9},{%0,%1,%2,%3};"
        : "+f"(d[0]), "+f"(d[1]), "+f"(d[2]), "+f"(d[3])
        : "r"(a[0]), "r"(a[1]), "r"(a[2]), "r"(a[3]), "r"(b[0]), "r"(b[1]));
}
__device__ __forceinline__ void ldsm4(uint32_t addr, uint32_t* r) {
    asm volatile("ldmatrix.sync.aligned.m8n8.x4.shared.b16 {%0,%1,%2,%3}, [%4];"
        : "=r"(r[0]), "=r"(r[1]), "=r"(r[2]), "=r"(r[3]) : "r"(addr));
}
// a-frag (m16n8k16): rows R..R+15, k16-step ks (chunks ks*2, ks*2+1)
__device__ __forceinline__ void fragA(uint32_t tbase, int R, int ks, int lane, uint32_t* a) {
    int mi = lane >> 3, ri = lane & 7;
    int r = R + ri + (mi & 1) * 8;
    int c = ks * 2 + (mi >> 1);
    ldsm4(tbase + swz64(r, c), a);
}
// b-frags for TWO n8 tiles (rows N0..N0+15): [b0_t0,b1_t0,b0_t1,b1_t1]
__device__ __forceinline__ void fragB(uint32_t tbase, int N0, int ks, int lane, uint32_t* b) {
    int mi = lane >> 3, ri = lane & 7;
    int r = N0 + ri + (mi >> 1) * 8;
    int c = ks * 2 + (mi & 1);
    ldsm4(tbase + swz64(r, c), b);
}

// ------- 128x32-half tile (8KB), half source -------
struct U8 { uint4 a, b; };
__device__ __forceinline__ U8 ldgH(const __half* g, size_t ld, int kb, int tid) {
    int row = tid >> 1, c0 = (tid & 1) * 16;
    const __half* p = g + (size_t)row * ld + kb + c0;
    U8 r; r.a = *(const uint4*)p; r.b = *(const uint4*)(p + 8);
    return r;
}
__device__ __forceinline__ void stsH(char* tile, U8 s, int tid) {
    int row = tid >> 1, c0 = (tid & 1) * 2;
    *(uint4*)(tile + swz64(row, c0))     = s.a;
    *(uint4*)(tile + swz64(row, c0 + 1)) = s.b;
}
// ------- 64x32-half tile (4KB), fp32 source with convert -------
struct W8 { float4 a, b; };
__device__ __forceinline__ W8 ldgW(const float* g, int ld, int kb, int tid) {
    int row = tid >> 2, c = tid & 3;
    const float* p = g + (size_t)row * ld + kb + c * 8;
    W8 r; r.a = *(const float4*)p; r.b = *(const float4*)(p + 4);
    return r;
}
__device__ __forceinline__ void stsW(char* tile, W8 s, int tid) {
    int row = tid >> 2, c = tid & 3;
    uint4 h;
    h.x = f2h2(s.a.x, s.a.y); h.y = f2h2(s.a.z, s.a.w);
    h.z = f2h2(s.b.x, s.b.y); h.w = f2h2(s.b.z, s.b.w);
    *(uint4*)(tile + swz64(row, c)) = h;
}

// ============================================================
// Kernel 1: row norms of F + convert F -> g_Fh
// ============================================================
__global__ void norm_cvt_kernel(const float* __restrict__ F)
{
    int row = blockIdx.x, tid = threadIdx.x;   // 128 threads
    const float4* fr = (const float4*)(F + (size_t)row * DDIM);
    float4 v = fr[tid];
    float s = v.x*v.x + v.y*v.y + v.z*v.z + v.w*v.w;
    uint2 h; h.x = f2h2(v.x, v.y); h.y = f2h2(v.z, v.w);
    *(uint2*)(g_Fh + (size_t)row * DDIM + tid * 4) = h;
    #pragma unroll
    for (int o = 16; o > 0; o >>= 1) s += __shfl_xor_sync(0xffffffffu, s, o);
    __shared__ float red[4];
    if ((tid & 31) == 0) red[tid >> 5] = s;
    __syncthreads();
    if (tid == 0) g_norm[row] = red[0] + red[1] + red[2] + red[3];
}

// ============================================================
// Kernel 2: Q/K/V = F @ W^T + b  (fp16 mma). Block 128x64, warp 32x32.
// Outputs g_Qh, g_Kh (row-major half), g_Vth (transposed half).
// ============================================================
__global__ __launch_bounds__(256) void qkv_h(
    const float* __restrict__ Wq, const float* __restrict__ bq,
    const float* __restrict__ Wk, const float* __restrict__ bk,
    const float* __restrict__ Wv, const float* __restrict__ bv)
{
    __shared__ char smem[2 * 20 * 1024];
    const int tid = threadIdx.x, lane = tid & 31, wid = tid >> 5;
    const int wm = wid & 3, wn = wid >> 2;
    const int rowBase = blockIdx.y * 128, colBase = blockIdx.x * 64;

    float aq[2][4][4] = {}, ak[2][4][4] = {}, avv[2][4][4] = {};

    const __half* Fb = g_Fh + (size_t)rowBase * DDIM;
    const float* Qb = Wq + (size_t)colBase * DDIM;
    const float* Kb = Wk + (size_t)colBase * DDIM;
    const float* Vb = Wv + (size_t)colBase * DDIM;

    U8 pf = ldgH(Fb, DDIM, 0, tid);
    W8 pq = ldgW(Qb, DDIM, 0, tid);
    W8 pk = ldgW(Kb, DDIM, 0, tid);
    W8 pv = ldgW(Vb, DDIM, 0, tid);
    char* buf0 = smem; char* buf1 = smem + 20 * 1024;
    stsH(buf0, pf, tid);
    stsW(buf0 +  8192, pq, tid);
    stsW(buf0 + 12288, pk, tid);
    stsW(buf0 + 16384, pv, tid);
    __syncthreads();

    const int NKB = DDIM / 32;   // 16
    for (int kb = 0; kb < NKB; kb++) {
        if (kb + 1 < NKB) {
            int k = (kb + 1) * 32;
            pf = ldgH(Fb, DDIM, k, tid);
            pq = ldgW(Qb, DDIM, k, tid);
            pk = ldgW(Kb, DDIM, k, tid);
            pv = ldgW(Vb, DDIM, k, tid);
        }
        uint32_t su = s2u((kb & 1) ? buf1 : buf0);
        #pragma unroll
        for (int ks = 0; ks < 2; ks++) {
            uint32_t a[2][4];
            fragA(su, wm * 32,      ks, lane, a[0]);
            fragA(su, wm * 32 + 16, ks, lane, a[1]);
            #pragma unroll
            for (int p = 0; p < 2; p++) {
                uint32_t b[4];
                fragB(su + 8192, wn * 32 + p * 16, ks, lane, b);
                #pragma unroll
                for (int tm = 0; tm < 2; tm++) {
                    mma16(aq[tm][2*p],   a[tm], b);
                    mma16(aq[tm][2*p+1], a[tm], b + 2);
                }
                fragB(su + 12288, wn * 32 + p * 16, ks, lane, b);
                #pragma unroll
                for (int tm = 0; tm < 2; tm++) {
                    mma16(ak[tm][2*p],   a[tm], b);
                    mma16(ak[tm][2*p+1], a[tm], b + 2);
                }
                fragB(su + 16384, wn * 32 + p * 16, ks, lane, b);
                #pragma unroll
                for (int tm = 0; tm < 2; tm++) {
                    mma16(avv[tm][2*p],   a[tm], b);
                    mma16(avv[tm][2*p+1], a[tm], b + 2);
                }
            }
        }
        char* nxt = (kb & 1) ? buf0 : buf1;
        if (kb + 1 < NKB) {
            stsH(nxt, pf, tid);
            stsW(nxt +  8192, pq, tid);
            stsW(nxt + 12288, pk, tid);
            stsW(nxt + 16384, pv, tid);
        }
        __syncthreads();
    }

    const int gr = lane >> 2, tg = lane & 3;
    #pragma unroll
    for (int tm = 0; tm < 2; tm++) {
        int r0 = rowBase + wm * 32 + tm * 16 + gr, r1 = r0 + 8;
        #pragma unroll
        for (int tn = 0; tn < 4; tn++) {
            int c = colBase + wn * 32 + tn * 8 + 2 * tg;
            float bq0 = bq[c], bq1 = bq[c+1];
            float bk0 = bk[c], bk1 = bk[c+1];
            float bv0 = bv[c], bv1 = bv[c+1];
            float* A = aq[tm][tn];
            *(uint32_t*)(g_Qh + (size_t)r0 * DDIM + c) = f2h2(A[0] + bq0, A[1] + bq1);
            *(uint32_t*)(g_Qh + (size_t)r1 * DDIM + c) = f2h2(A[2] + bq0, A[3] + bq1);
            A = ak[tm][tn];
            *(uint32_t*)(g_Kh + (size_t)r0 * DDIM + c) = f2h2(A[0] + bk0, A[1] + bk1);
            *(uint32_t*)(g_Kh + (size_t)r1 * DDIM + c) = f2h2(A[2] + bk0, A[3] + bk1);
            A = avv[tm][tn];
            g_Vth[(size_t)c     * PP + r0] = __float2half(A[0] + bv0);
            g_Vth[(size_t)(c+1) * PP + r0] = __float2half(A[1] + bv1);
            g_Vth[(size_t)c     * PP + r1] = __float2half(A[2] + bv0);
            g_Vth[(size_t)(c+1) * PP + r1] = __float2half(A[3] + bv1);
        }
    }
}

// ============================================================
// Kernel 3: S=QK^T and G=FF^T fused (fp16 mma). Block 128x128,
// 8 warps (4m x 2n), warp 32x64. Dynamic smem 64KB.
// ============================================================
__global__ __launch_bounds__(256) void logits_h(
    const float* __restrict__ lamP, float* __restrict__ dist_out)
{
    extern __shared__ char dsm[];
    const int tid = threadIdx.x, lane = tid & 31, wid = tid >> 5;
    const int wm = wid & 3, wn = wid >> 2;
    const int rowBase = blockIdx.y * 128, colBase = blockIdx.x * 128;

    float accS[2][8][4] = {}, accG[2][8][4] = {};

    const __half* Qb = g_Qh + (size_t)rowBase * DDIM;
    const __half* Fr = g_Fh + (size_t)rowBase * DDIM;
    const __half* Kb = g_Kh + (size_t)colBase * DDIM;
    const __half* Cb = g_Fh + (size_t)colBase * DDIM;

    U8 s0 = ldgH(Qb, DDIM, 0, tid);
    U8 s1 = ldgH(Fr, DDIM, 0, tid);
    U8 s2 = ldgH(Kb, DDIM, 0, tid);
    U8 s3 = ldgH(Cb, DDIM, 0, tid);
    stsH(dsm,         s0, tid);
    stsH(dsm +  8192, s1, tid);
    stsH(dsm + 16384, s2, tid);
    stsH(dsm + 24576, s3, tid);
    __syncthreads();

    const int NKB = DDIM / 32;   // 16
    for (int kb = 0; kb < NKB; kb++) {
        if (kb + 1 < NKB) {
            int k = (kb + 1) * 32;
            s0 = ldgH(Qb, DDIM, k, tid);
            s1 = ldgH(Fr, DDIM, k, tid);
            s2 = ldgH(Kb, DDIM, k, tid);
            s3 = ldgH(Cb, DDIM, k, tid);
        }
        uint32_t su = s2u(dsm + (kb & 1) * 32768);
        #pragma unroll
        for (int ks = 0; ks < 2; ks++) {
            {   // S = Q K^T
                uint32_t a[2][4];
                fragA(su, wm * 32,      ks, lane, a[0]);
                fragA(su, wm * 32 + 16, ks, lane, a[1]);
                #pragma unroll
                for (int p = 0; p < 4; p++) {
                    uint32_t b[4];
                    fragB(su + 16384, wn * 64 + p * 16, ks, lane, b);
                    #pragma unroll
                    for (int tm = 0; tm < 2; tm++) {
                        mma16(accS[tm][2*p],   a[tm], b);
                        mma16(accS[tm][2*p+1], a[tm], b + 2);
                    }
                }
            }
            {   // G = F F^T
                uint32_t a[2][4];
                fragA(su + 8192, wm * 32,      ks, lane, a[0]);
                fragA(su + 8192, wm * 32 + 16, ks, lane, a[1]);
                #pragma unroll
                for (int p = 0; p < 4; p++) {
                    uint32_t b[4];
                    fragB(su + 24576, wn * 64 + p * 16, ks, lane, b);
                    #pragma unroll
                    for (int tm = 0; tm < 2; tm++) {
                        mma16(accG[tm][2*p],   a[tm], b);
                        mma16(accG[tm][2*p+1], a[tm], b + 2);
                    }
                }
            }
        }
        char* nxt = dsm + ((kb + 1) & 1) * 32768;
        if (kb + 1 < NKB) {
            stsH(nxt,         s0, tid);
            stsH(nxt +  8192, s1, tid);
            stsH(nxt + 16384, s2, tid);
            stsH(nxt + 24576, s3, tid);
        }
        __syncthreads();
    }

    const int gr = lane >> 2, tg = lane & 3;
    const float lam = *lamP;
    const float isd = 0.044194173824159216f;  // 1/sqrt(512)
    #pragma unroll
    for (int tm = 0; tm < 2; tm++) {
        int r0 = rowBase + wm * 32 + tm * 16 + gr, r1 = r0 + 8;
        float n0 = g_norm[r0], n1 = g_norm[r1];
        #pragma unroll
        for (int tn = 0; tn < 8; tn++) {
            int c = colBase + wn * 64 + tn * 8 + 2 * tg;
            float nc0 = g_norm[c], nc1 = g_norm[c+1];
            float* S = accS[tm][tn];
            float* G = accG[tm][tn];
            float d00 = sqrtf(fmaxf(n0 + nc0 - 2.f * G[0], 0.f));
            float d01 = sqrtf(fmaxf(n0 + nc1 - 2.f * G[1], 0.f));
            float d10 = sqrtf(fmaxf(n1 + nc0 - 2.f * G[2], 0.f));
            float d11 = sqrtf(fmaxf(n1 + nc1 - 2.f * G[3], 0.f));
            size_t o0 = (size_t)r0 * PP + c, o1 = (size_t)r1 * PP + c;
            *(float2*)(dist_out + o0) = make_float2(d00, d01);
            *(float2*)(dist_out + o1) = make_float2(d10, d11);
            *(float2*)(g_T + o0) = make_float2(S[0]*isd - lam*d00, S[1]*isd - lam*d01);
            *(float2*)(g_T + o1) = make_float2(S[2]*isd - lam*d10, S[3]*isd - lam*d11);
        }
    }
}

// ============================================================
// Kernel 4: row softmax over g_T; write exp probs as half to g_Th;
// store 1/sum in g_inv.
// ============================================================
__global__ __launch_bounds__(256) void softmax_h()
{
    int row = blockIdx.x;
    const float* T = g_T + (size_t)row * PP;
    __half* Th = g_Th + (size_t)row * PP;
    int tid = threadIdx.x;

    float m = -3.4e38f;
    for (int i = tid * 8; i < PP; i += 2048) {
        float4 v0 = *(const float4*)(T + i);
        float4 v1 = *(const float4*)(T + i + 4);
        m = fmaxf(m, fmaxf(fmaxf(v0.x, v0.y), fmaxf(v0.z, v0.w)));
        m = fmaxf(m, fmaxf(fmaxf(v1.x, v1.y), fmaxf(v1.z, v1.w)));
    }
    __shared__ float red[8];
    #pragma unroll
    for (int o = 16; o > 0; o >>= 1) m = fmaxf(m, __shfl_xor_sync(0xffffffffu, m, o));
    if ((tid & 31) == 0) red[tid >> 5] = m;
    __syncthreads();
    if (tid == 0) {
        float bm = red[0];
        #pragma unroll
        for (int w = 1; w < 8; w++) bm = fmaxf(bm, red[w]);
        red[0] = bm;
    }
    __syncthreads();
    m = red[0];
    __syncthreads();

    float s = 0.f;
    for (int i = tid * 8; i < PP; i += 2048) {
        float4 v0 = *(const float4*)(T + i);
        float4 v1 = *(const float4*)(T + i + 4);
        float e0 = __expf(v0.x - m), e1 = __expf(v0.y - m);
        float e2 = __expf(v0.z - m), e3 = __expf(v0.w - m);
        float e4 = __expf(v1.x - m), e5 = __expf(v1.y - m);
        float e6 = __expf(v1.z - m), e7 = __expf(v1.w - m);
        s += e0 + e1 + e2 + e3 + e4 + e5 + e6 + e7;
        uint4 h;
        h.x = f2h2(e0, e1); h.y = f2h2(e2, e3);
        h.z = f2h2(e4, e5); h.w = f2h2(e6, e7);
        *(uint4*)(Th + i) = h;
    }
    #pragma unroll
    for (int o = 16; o > 0; o >>= 1) s += __shfl_xor_sync(0xffffffffu, s, o);
    if ((tid & 31) == 0) red[tid >> 5] = s;
    __syncthreads();
    if (tid == 0) {
        float bs = red[0];
        #pragma unroll
        for (int w = 1; w < 8; w++) bs += red[w];
        g_inv[row] = 1.f / bs;
    }
}

// ============================================================
// Kernel 5: F_out = (probs @ V) * (1/sum). fp16 mma.
// Block 128x128 (rows x features), warp 32x64. A=g_Th, B=g_Vth.
// ============================================================
__global__ __launch_bounds__(256) void av_h(float* __restrict__ out)
{
    __shared__ char smem[2 * 16 * 1024];
    const int tid = threadIdx.x, lane = tid & 31, wid = tid >> 5;
    const int wm = wid & 3, wn = wid >> 2;
    const int rowBase = blockIdx.y * 128, colBase = blockIdx.x * 128;

    float acc[2][8][4] = {};

    const __half* Ab = g_Th  + (size_t)rowBase * PP;
    const __half* Bb = g_Vth + (size_t)colBase * PP;

    U8 s0 = ldgH(Ab, PP, 0, tid);
    U8 s1 = ldgH(Bb, PP, 0, tid);
    char* buf0 = smem; char* buf1 = smem + 16 * 1024;
    stsH(buf0,        s0, tid);
    stsH(buf0 + 8192, s1, tid);
    __syncthreads();

    const int NKB = PP / 32;   // 256
    for (int kb = 0; kb < NKB; kb++) {
        if (kb + 1 < NKB) {
            int k = (kb + 1) * 32;
            s0 = ldgH(Ab, PP, k, tid);
            s1 = ldgH(Bb, PP, k, tid);
        }
        uint32_t su = s2u((kb & 1) ? buf1 : buf0);
        #pragma unroll
        for (int ks = 0; ks < 2; ks++) {
            uint32_t a[2][4];
            fragA(su, wm * 32,      ks, lane, a[0]);
            fragA(su, wm * 32 + 16, ks, lane, a[1]);
            #pragma unroll
            for (int p = 0; p < 4; p++) {
                uint32_t b[4];
                fragB(su + 8192, wn * 64 + p * 16, ks, lane, b);
                #pragma unroll
                for (int tm = 0; tm < 2; tm++) {
                    mma16(acc[tm][2*p],   a[tm], b);
                    mma16(acc[tm][2*p+1], a[tm], b + 2);
                }
            }
        }
        char* nxt = (kb & 1) ? buf0 : buf1;
        if (kb + 1 < NKB) {
            stsH(nxt,        s0, tid);
            stsH(nxt + 8192, s1, tid);
        }
        __syncthreads();
    }

    const int gr = lane >> 2, tg = lane & 3;
    #pragma unroll
    for (int tm = 0; tm < 2; tm++) {
        int r0 = rowBase + wm * 32 + tm * 16 + gr, r1 = r0 + 8;
        float i0 = g_inv[r0], i1 = g_inv[r1];
        #pragma unroll
        for (int tn = 0; tn < 8; tn++) {
            int c = colBase + wn * 64 + tn * 8 + 2 * tg;
            float* A = acc[tm][tn];
            *(float2*)(out + (size_t)r0 * DDIM + c) = make_float2(A[0]*i0, A[1]*i0);
            *(float2*)(out + (size_t)r1 * DDIM + c) = make_float2(A[2]*i1, A[3]*i1);
        }
    }
}

// ============================================================
extern "C" void kernel_launch(void* const* d_in, const int* in_sizes, int n_in,
                              void* d_out, int out_size)
{
    const float* F   = (const float*)d_in[0];
    const float* Wq  = (const float*)d_in[1];
    const float* bq  = (const float*)d_in[2];
    const float* Wk  = (const float*)d_in[3];
    const float* bk  = (const float*)d_in[4];
    const float* Wv  = (const float*)d_in[5];
    const float* bv  = (const float*)d_in[6];
    const float* lam = (const float*)d_in[7];

    float* out  = (float*)d_out;
    float* Fout = out;                        // [P, D]
    float* dist = out + (size_t)PP * DDIM;    // [P, P]

    static bool attr_done = false;
    if (!attr_done) {
        cudaFuncSetAttribute(logits_h, cudaFuncAttributeMaxDynamicSharedMemorySize, 65536);
        attr_done = true;
    }

    norm_cvt_kernel<<<PP, 128>>>(F);
    qkv_h<<<dim3(DDIM/64, PP/128), 256>>>(Wq, bq, Wk, bk, Wv, bv);
    logits_h<<<dim3(PP/128, PP/128), 256, 65536>>>(lam, dist);
    softmax_h<<<PP, 256>>>();
    av_h<<<dim3(DDIM/128, PP/128), 256>>>(Fout);
}

// round 8
// speedup vs baseline: 5.5221x; 1.1750x over previous
#include <cuda_runtime.h>
#include <cuda_fp16.h>
#include <math.h>
#include <stdint.h>

#define PP 8192
#define DDIM 512

// ---- scratch (device globals) ----
__device__ __half g_Qh[PP * DDIM];
__device__ __half g_Kh[PP * DDIM];
__device__ __half g_Fh[PP * DDIM];
__device__ __half g_Vth[DDIM * PP];          // V transposed: [feature][position]
__device__ __half g_Th[(size_t)PP * PP];     // unnormalized exp probs (fp16), 128 MB
__device__ float  g_psum[PP * 64];           // per (row, colTile) partial sums
__device__ float  g_norm[PP];
__device__ float  g_tdiag[PP];
__device__ float  g_inv[PP];

// ---------------- helpers ----------------
__device__ __forceinline__ uint32_t s2u(const void* p) {
    return (uint32_t)__cvta_generic_to_shared(p);
}
__device__ __forceinline__ uint32_t f2h2(float a, float b) {
    __half2 h = __floats2half2_rn(a, b);
    return *reinterpret_cast<uint32_t*>(&h);
}
// tile rows of 32 halves (64B), 16B chunks XOR-swizzled
__device__ __forceinline__ int swz64(int r, int c) {
    return r * 64 + ((c ^ ((r >> 1) & 3)) << 4);
}
__device__ __forceinline__ void mma16(float* d, const uint32_t* a, const uint32_t* b) {
    asm volatile(
        "mma.sync.aligned.m16n8k16.row.col.f32.f16.f16.f32 "
        "{%0,%1,%2,%3},{%4,%5,%6,%7},{%8,%9},{%0,%1,%2,%3};"
        : "+f"(d[0]), "+f"(d[1]), "+f"(d[2]), "+f"(d[3])
        : "r"(a[0]), "r"(a[1]), "r"(a[2]), "r"(a[3]), "r"(b[0]), "r"(b[1]));
}
__device__ __forceinline__ void ldsm4(uint32_t addr, uint32_t* r) {
    asm volatile("ldmatrix.sync.aligned.m8n8.x4.shared.b16 {%0,%1,%2,%3}, [%4];"
        : "=r"(r[0]), "=r"(r[1]), "=r"(r[2]), "=r"(r[3]) : "r"(addr));
}
__device__ __forceinline__ void fragA(uint32_t tbase, int R, int ks, int lane, uint32_t* a) {
    int mi = lane >> 3, ri = lane & 7;
    int r = R + ri + (mi & 1) * 8;
    int c = ks * 2 + (mi >> 1);
    ldsm4(tbase + swz64(r, c), a);
}
__device__ __forceinline__ void fragB(uint32_t tbase, int N0, int ks, int lane, uint32_t* b) {
    int mi = lane >> 3, ri = lane & 7;
    int r = N0 + ri + (mi >> 1) * 8;
    int c = ks * 2 + (mi & 1);
    ldsm4(tbase + swz64(r, c), b);
}
// ---- cp.async ----
__device__ __forceinline__ void cpa16(uint32_t dst, const void* src) {
    asm volatile("cp.async.cg.shared.global [%0], [%1], 16;" :: "r"(dst), "l"(src));
}
__device__ __forceinline__ void cp_commit() {
    asm volatile("cp.async.commit_group;" ::: "memory");
}
template<int N>
__device__ __forceinline__ void cp_wait() {
    asm volatile("cp.async.wait_group %0;" :: "n"(N) : "memory");
}

// ------- reg-staged tiles for qkv (unchanged from R7) -------
struct U8 { uint4 a, b; };
__device__ __forceinline__ U8 ldgH(const __half* g, size_t ld, int kb, int tid) {
    int row = tid >> 1, c0 = (tid & 1) * 16;
    const __half* p = g + (size_t)row * ld + kb + c0;
    U8 r; r.a = *(const uint4*)p; r.b = *(const uint4*)(p + 8);
    return r;
}
__device__ __forceinline__ void stsH(char* tile, U8 s, int tid) {
    int row = tid >> 1, c0 = (tid & 1) * 2;
    *(uint4*)(tile + swz64(row, c0))     = s.a;
    *(uint4*)(tile + swz64(row, c0 + 1)) = s.b;
}
struct W8 { float4 a, b; };
__device__ __forceinline__ W8 ldgW(const float* g, int ld, int kb, int tid) {
    int row = tid >> 2, c = tid & 3;
    const float* p = g + (size_t)row * ld + kb + c * 8;
    W8 r; r.a = *(const float4*)p; r.b = *(const float4*)(p + 4);
    return r;
}
__device__ __forceinline__ void stsW(char* tile, W8 s, int tid) {
    int row = tid >> 2, c = tid & 3;
    uint4 h;
    h.x = f2h2(s.a.x, s.a.y); h.y = f2h2(s.a.z, s.a.w);
    h.z = f2h2(s.b.x, s.b.y); h.w = f2h2(s.b.z, s.b.w);
    *(uint4*)(tile + swz64(row, c)) = h;
}

// ============================================================
// Kernel 1: row norms of F + convert F -> g_Fh
// ============================================================
__global__ void norm_cvt_kernel(const float* __restrict__ F)
{
    int row = blockIdx.x, tid = threadIdx.x;   // 128 threads
    const float4* fr = (const float4*)(F + (size_t)row * DDIM);
    float4 v = fr[tid];
    float s = v.x*v.x + v.y*v.y + v.z*v.z + v.w*v.w;
    uint2 h; h.x = f2h2(v.x, v.y); h.y = f2h2(v.z, v.w);
    *(uint2*)(g_Fh + (size_t)row * DDIM + tid * 4) = h;
    #pragma unroll
    for (int o = 16; o > 0; o >>= 1) s += __shfl_xor_sync(0xffffffffu, s, o);
    __shared__ float red[4];
    if ((tid & 31) == 0) red[tid >> 5] = s;
    __syncthreads();
    if (tid == 0) g_norm[row] = red[0] + red[1] + red[2] + red[3];
}

// ============================================================
// Kernel 2: Q/K/V = F @ W^T + b (fp16 mma). Outputs Qh,Kh,Vth.
// ============================================================
__global__ __launch_bounds__(256) void qkv_h(
    const float* __restrict__ Wq, const float* __restrict__ bq,
    const float* __restrict__ Wk, const float* __restrict__ bk,
    const float* __restrict__ Wv, const float* __restrict__ bv)
{
    __shared__ char smem[2 * 20 * 1024];
    const int tid = threadIdx.x, lane = tid & 31, wid = tid >> 5;
    const int wm = wid & 3, wn = wid >> 2;
    const int rowBase = blockIdx.y * 128, colBase = blockIdx.x * 64;

    float aq[2][4][4] = {}, ak[2][4][4] = {}, avv[2][4][4] = {};

    const __half* Fb = g_Fh + (size_t)rowBase * DDIM;
    const float* Qb = Wq + (size_t)colBase * DDIM;
    const float* Kb = Wk + (size_t)colBase * DDIM;
    const float* Vb = Wv + (size_t)colBase * DDIM;

    U8 pf = ldgH(Fb, DDIM, 0, tid);
    W8 pq = ldgW(Qb, DDIM, 0, tid);
    W8 pk = ldgW(Kb, DDIM, 0, tid);
    W8 pv = ldgW(Vb, DDIM, 0, tid);
    char* buf0 = smem; char* buf1 = smem + 20 * 1024;
    stsH(buf0, pf, tid);
    stsW(buf0 +  8192, pq, tid);
    stsW(buf0 + 12288, pk, tid);
    stsW(buf0 + 16384, pv, tid);
    __syncthreads();

    const int NKB = DDIM / 32;   // 16
    for (int kb = 0; kb < NKB; kb++) {
        if (kb + 1 < NKB) {
            int k = (kb + 1) * 32;
            pf = ldgH(Fb, DDIM, k, tid);
            pq = ldgW(Qb, DDIM, k, tid);
            pk = ldgW(Kb, DDIM, k, tid);
            pv = ldgW(Vb, DDIM, k, tid);
        }
        uint32_t su = s2u((kb & 1) ? buf1 : buf0);
        #pragma unroll
        for (int ks = 0; ks < 2; ks++) {
            uint32_t a[2][4];
            fragA(su, wm * 32,      ks, lane, a[0]);
            fragA(su, wm * 32 + 16, ks, lane, a[1]);
            #pragma unroll
            for (int p = 0; p < 2; p++) {
                uint32_t b[4];
                fragB(su + 8192, wn * 32 + p * 16, ks, lane, b);
                #pragma unroll
                for (int tm = 0; tm < 2; tm++) {
                    mma16(aq[tm][2*p],   a[tm], b);
                    mma16(aq[tm][2*p+1], a[tm], b + 2);
                }
                fragB(su + 12288, wn * 32 + p * 16, ks, lane, b);
                #pragma unroll
                for (int tm = 0; tm < 2; tm++) {
                    mma16(ak[tm][2*p],   a[tm], b);
                    mma16(ak[tm][2*p+1], a[tm], b + 2);
                }
                fragB(su + 16384, wn * 32 + p * 16, ks, lane, b);
                #pragma unroll
                for (int tm = 0; tm < 2; tm++) {
                    mma16(avv[tm][2*p],   a[tm], b);
                    mma16(avv[tm][2*p+1], a[tm], b + 2);
                }
            }
        }
        char* nxt = (kb & 1) ? buf0 : buf1;
        if (kb + 1 < NKB) {
            stsH(nxt, pf, tid);
            stsW(nxt +  8192, pq, tid);
            stsW(nxt + 12288, pk, tid);
            stsW(nxt + 16384, pv, tid);
        }
        __syncthreads();
    }

    const int gr = lane >> 2, tg = lane & 3;
    #pragma unroll
    for (int tm = 0; tm < 2; tm++) {
        int r0 = rowBase + wm * 32 + tm * 16 + gr, r1 = r0 + 8;
        #pragma unroll
        for (int tn = 0; tn < 4; tn++) {
            int c = colBase + wn * 32 + tn * 8 + 2 * tg;
            float bq0 = bq[c], bq1 = bq[c+1];
            float bk0 = bk[c], bk1 = bk[c+1];
            float bv0 = bv[c], bv1 = bv[c+1];
            float* A = aq[tm][tn];
            *(uint32_t*)(g_Qh + (size_t)r0 * DDIM + c) = f2h2(A[0] + bq0, A[1] + bq1);
            *(uint32_t*)(g_Qh + (size_t)r1 * DDIM + c) = f2h2(A[2] + bq0, A[3] + bq1);
            A = ak[tm][tn];
            *(uint32_t*)(g_Kh + (size_t)r0 * DDIM + c) = f2h2(A[0] + bk0, A[1] + bk1);
            *(uint32_t*)(g_Kh + (size_t)r1 * DDIM + c) = f2h2(A[2] + bk0, A[3] + bk1);
            A = avv[tm][tn];
            g_Vth[(size_t)c     * PP + r0] = __float2half(A[0] + bv0);
            g_Vth[(size_t)(c+1) * PP + r0] = __float2half(A[1] + bv1);
            g_Vth[(size_t)c     * PP + r1] = __float2half(A[2] + bv0);
            g_Vth[(size_t)(c+1) * PP + r1] = __float2half(A[3] + bv1);
        }
    }
}

// ============================================================
// Kernel 3: tdiag[i] = (Q_i . K_i) / sqrt(d)
// ============================================================
__global__ void diag_kernel()
{
    int row = blockIdx.x, tid = threadIdx.x;   // 128 threads
    const __half* Q = g_Qh + (size_t)row * DDIM + tid * 4;
    const __half* K = g_Kh + (size_t)row * DDIM + tid * 4;
    uint2 qa = *(const uint2*)Q;
    uint2 ka = *(const uint2*)K;
    __half2 q0 = *(__half2*)&qa.x, q1 = *(__half2*)&qa.y;
    __half2 k0 = *(__half2*)&ka.x, k1 = *(__half2*)&ka.y;
    float2 qf0 = __half22float2(q0), qf1 = __half22float2(q1);
    float2 kf0 = __half22float2(k0), kf1 = __half22float2(k1);
    float s = qf0.x*kf0.x + qf0.y*kf0.y + qf1.x*kf1.x + qf1.y*kf1.y;
    #pragma unroll
    for (int o = 16; o > 0; o >>= 1) s += __shfl_xor_sync(0xffffffffu, s, o);
    __shared__ float red[4];
    if ((tid & 31) == 0) red[tid >> 5] = s;
    __syncthreads();
    if (tid == 0)
        g_tdiag[row] = (red[0] + red[1] + red[2] + red[3]) * 0.044194173824159216f;
}

// ============================================================
// Kernel 4: S=QK^T and G=FF^T fused (fp16 mma, cp.async 4-stage).
// Epilogue: dist out; E=exp(S*isd - lam*d - tdiag) -> g_Th fp16;
// per-(row,colTile) partial sums -> g_psum.
// ============================================================
__device__ __forceinline__ void lg_issue(uint32_t sbase, int stg, int kb, int tid,
    const __half* Qb, const __half* Fr, const __half* Kb, const __half* Cb)
{
    int row = tid >> 1;
    int ch0 = (tid & 1) * 2;
    uint32_t so = sbase + stg * 32768;
    size_t off = (size_t)row * DDIM + kb + ch0 * 8;
    cpa16(so +         swz64(row, ch0),     Qb + off);
    cpa16(so +         swz64(row, ch0 + 1), Qb + off + 8);
    cpa16(so +  8192 + swz64(row, ch0),     Fr + off);
    cpa16(so +  8192 + swz64(row, ch0 + 1), Fr + off + 8);
    cpa16(so + 16384 + swz64(row, ch0),     Kb + off);
    cpa16(so + 16384 + swz64(row, ch0 + 1), Kb + off + 8);
    cpa16(so + 24576 + swz64(row, ch0),     Cb + off);
    cpa16(so + 24576 + swz64(row, ch0 + 1), Cb + off + 8);
}

__global__ __launch_bounds__(256) void logits_e(
    const float* __restrict__ lamP, float* __restrict__ dist_out)
{
    extern __shared__ char dsm[];
    __shared__ float ps[128][2];
    const uint32_t sbase = s2u(dsm);
    const int tid = threadIdx.x, lane = tid & 31, wid = tid >> 5;
    const int wm = wid & 3, wn = wid >> 2;
    const int rowBase = blockIdx.y * 128, colBase = blockIdx.x * 128;

    float accS[2][8][4] = {}, accG[2][8][4] = {};

    const __half* Qb = g_Qh + (size_t)rowBase * DDIM;
    const __half* Fr = g_Fh + (size_t)rowBase * DDIM;
    const __half* Kb = g_Kh + (size_t)colBase * DDIM;
    const __half* Cb = g_Fh + (size_t)colBase * DDIM;

    const int NKB = DDIM / 32;   // 16
    #pragma unroll
    for (int s = 0; s < 3; s++) {
        lg_issue(sbase, s, s * 32, tid, Qb, Fr, Kb, Cb);
        cp_commit();
    }

    for (int kb = 0; kb < NKB; kb++) {
        cp_wait<2>();
        __syncthreads();
        if (kb + 3 < NKB)
            lg_issue(sbase, (kb + 3) & 3, (kb + 3) * 32, tid, Qb, Fr, Kb, Cb);
        cp_commit();

        uint32_t su = sbase + (kb & 3) * 32768;
        #pragma unroll
        for (int ks = 0; ks < 2; ks++) {
            {   // S = Q K^T
                uint32_t a[2][4];
                fragA(su, wm * 32,      ks, lane, a[0]);
                fragA(su, wm * 32 + 16, ks, lane, a[1]);
                #pragma unroll
                for (int p = 0; p < 4; p++) {
                    uint32_t b[4];
                    fragB(su + 16384, wn * 64 + p * 16, ks, lane, b);
                    #pragma unroll
                    for (int tm = 0; tm < 2; tm++) {
                        mma16(accS[tm][2*p],   a[tm], b);
                        mma16(accS[tm][2*p+1], a[tm], b + 2);
                    }
                }
            }
            {   // G = F F^T
                uint32_t a[2][4];
                fragA(su + 8192, wm * 32,      ks, lane, a[0]);
                fragA(su + 8192, wm * 32 + 16, ks, lane, a[1]);
                #pragma unroll
                for (int p = 0; p < 4; p++) {
                    uint32_t b[4];
                    fragB(su + 24576, wn * 64 + p * 16, ks, lane, b);
                    #pragma unroll
                    for (int tm = 0; tm < 2; tm++) {
                        mma16(accG[tm][2*p],   a[tm], b);
                        mma16(accG[tm][2*p+1], a[tm], b + 2);
                    }
                }
            }
        }
    }

    const int gr = lane >> 2, tg = lane & 3;
    const float lam = *lamP;
    const float isd = 0.044194173824159216f;  // 1/sqrt(512)
    float rs[2][2];
    #pragma unroll
    for (int tm = 0; tm < 2; tm++) {
        int r0 = rowBase + wm * 32 + tm * 16 + gr, r1 = r0 + 8;
        float n0 = g_norm[r0], n1 = g_norm[r1];
        float td0 = g_tdiag[r0], td1 = g_tdiag[r1];
        float s0 = 0.f, s1 = 0.f;
        #pragma unroll
        for (int tn = 0; tn < 8; tn++) {
            int c = colBase + wn * 64 + tn * 8 + 2 * tg;
            float nc0 = g_norm[c], nc1 = g_norm[c+1];
            float* S = accS[tm][tn];
            float* G = accG[tm][tn];
            float d00 = sqrtf(fmaxf(n0 + nc0 - 2.f * G[0], 0.f));
            float d01 = sqrtf(fmaxf(n0 + nc1 - 2.f * G[1], 0.f));
            float d10 = sqrtf(fmaxf(n1 + nc0 - 2.f * G[2], 0.f));
            float d11 = sqrtf(fmaxf(n1 + nc1 - 2.f * G[3], 0.f));
            size_t o0 = (size_t)r0 * PP + c, o1 = (size_t)r1 * PP + c;
            *(float2*)(dist_out + o0) = make_float2(d00, d01);
            *(float2*)(dist_out + o1) = make_float2(d10, d11);
            float e00 = __expf(fminf(S[0]*isd - lam*d00 - td0, 11.f));
            float e01 = __expf(fminf(S[1]*isd - lam*d01 - td0, 11.f));
            float e10 = __expf(fminf(S[2]*isd - lam*d10 - td1, 11.f));
            float e11 = __expf(fminf(S[3]*isd - lam*d11 - td1, 11.f));
            s0 += e00 + e01;
            s1 += e10 + e11;
            *(uint32_t*)(g_Th + o0) = f2h2(e00, e01);
            *(uint32_t*)(g_Th + o1) = f2h2(e10, e11);
        }
        rs[tm][0] = s0; rs[tm][1] = s1;
    }
    // reduce partial sums across tg lanes, combine wn halves, write g_psum
    #pragma unroll
    for (int tm = 0; tm < 2; tm++) {
        #pragma unroll
        for (int h = 0; h < 2; h++) {
            float s = rs[tm][h];
            s += __shfl_xor_sync(0xffffffffu, s, 1);
            s += __shfl_xor_sync(0xffffffffu, s, 2);
            if (tg == 0) ps[wm * 32 + tm * 16 + gr + h * 8][wn] = s;
        }
    }
    __syncthreads();
    if (tid < 128)
        g_psum[(size_t)(rowBase + tid) * 64 + blockIdx.x] = ps[tid][0] + ps[tid][1];
}

// ============================================================
// Kernel 5: g_inv[row] = 1 / sum over 64 col-tile partials
// ============================================================
__global__ void rowsum_kernel()
{
    int row = blockIdx.x, lane = threadIdx.x;  // 32 threads
    float s = g_psum[(size_t)row * 64 + lane] + g_psum[(size_t)row * 64 + 32 + lane];
    #pragma unroll
    for (int o = 16; o > 0; o >>= 1) s += __shfl_xor_sync(0xffffffffu, s, o);
    if (lane == 0) g_inv[row] = 1.f / s;
}

// ============================================================
// Kernel 6: F_out = (E @ V) * (1/sum). fp16 mma, cp.async 4-stage.
// ============================================================
__device__ __forceinline__ void av_issue(uint32_t sbase, int stg, int kb, int tid,
    const __half* Ab, const __half* Bb)
{
    int row = tid >> 1;
    int ch0 = (tid & 1) * 2;
    uint32_t so = sbase + stg * 16384;
    size_t off = (size_t)row * PP + kb + ch0 * 8;
    cpa16(so +        swz64(row, ch0),     Ab + off);
    cpa16(so +        swz64(row, ch0 + 1), Ab + off + 8);
    cpa16(so + 8192 + swz64(row, ch0),     Bb + off);
    cpa16(so + 8192 + swz64(row, ch0 + 1), Bb + off + 8);
}

__global__ __launch_bounds__(256) void av_e(float* __restrict__ out)
{
    extern __shared__ char dsm[];
    const uint32_t sbase = s2u(dsm);
    const int tid = threadIdx.x, lane = tid & 31, wid = tid >> 5;
    const int wm = wid & 3, wn = wid >> 2;
    const int rowBase = blockIdx.y * 128, colBase = blockIdx.x * 128;

    float acc[2][8][4] = {};

    const __half* Ab = g_Th  + (size_t)rowBase * PP;
    const __half* Bb = g_Vth + (size_t)colBase * PP;

    const int NKB = PP / 32;   // 256
    #pragma unroll
    for (int s = 0; s < 3; s++) {
        av_issue(sbase, s, s * 32, tid, Ab, Bb);
        cp_commit();
    }

    for (int kb = 0; kb < NKB; kb++) {
        cp_wait<2>();
        __syncthreads();
        if (kb + 3 < NKB)
            av_issue(sbase, (kb + 3) & 3, (kb + 3) * 32, tid, Ab, Bb);
        cp_commit();

        uint32_t su = sbase + (kb & 3) * 16384;
        #pragma unroll
        for (int ks = 0; ks < 2; ks++) {
            uint32_t a[2][4];
            fragA(su, wm * 32,      ks, lane, a[0]);
            fragA(su, wm * 32 + 16, ks, lane, a[1]);
            #pragma unroll
            for (int p = 0; p < 4; p++) {
                uint32_t b[4];
                fragB(su + 8192, wn * 64 + p * 16, ks, lane, b);
                #pragma unroll
                for (int tm = 0; tm < 2; tm++) {
                    mma16(acc[tm][2*p],   a[tm], b);
                    mma16(acc[tm][2*p+1], a[tm], b + 2);
                }
            }
        }
    }

    const int gr = lane >> 2, tg = lane & 3;
    #pragma unroll
    for (int tm = 0; tm < 2; tm++) {
        int r0 = rowBase + wm * 32 + tm * 16 + gr, r1 = r0 + 8;
        float i0 = g_inv[r0], i1 = g_inv[r1];
        #pragma unroll
        for (int tn = 0; tn < 8; tn++) {
            int c = colBase + wn * 64 + tn * 8 + 2 * tg;
            float* A = acc[tm][tn];
            *(float2*)(out + (size_t)r0 * DDIM + c) = make_float2(A[0]*i0, A[1]*i0);
            *(float2*)(out + (size_t)r1 * DDIM + c) = make_float2(A[2]*i1, A[3]*i1);
        }
    }
}

// ============================================================
extern "C" void kernel_launch(void* const* d_in, const int* in_sizes, int n_in,
                              void* d_out, int out_size)
{
    const float* F   = (const float*)d_in[0];
    const float* Wq  = (const float*)d_in[1];
    const float* bq  = (const float*)d_in[2];
    const float* Wk  = (const float*)d_in[3];
    const float* bk  = (const float*)d_in[4];
    const float* Wv  = (const float*)d_in[5];
    const float* bv  = (const float*)d_in[6];
    const float* lam = (const float*)d_in[7];

    float* out  = (float*)d_out;
    float* Fout = out;                        // [P, D]
    float* dist = out + (size_t)PP * DDIM;    // [P, P]

    static bool attr_done = false;
    if (!attr_done) {
        cudaFuncSetAttribute(logits_e, cudaFuncAttributeMaxDynamicSharedMemorySize, 131072);
        cudaFuncSetAttribute(av_e,     cudaFuncAttributeMaxDynamicSharedMemorySize, 65536);
        attr_done = true;
    }

    norm_cvt_kernel<<<PP, 128>>>(F);
    qkv_h<<<dim3(DDIM/64, PP/128), 256>>>(Wq, bq, Wk, bk, Wv, bv);
    diag_kernel<<<PP, 128>>>();
    logits_e<<<dim3(PP/128, PP/128), 256, 131072>>>(lam, dist);
    rowsum_kernel<<<PP, 32>>>();
    av_e<<<dim3(DDIM/128, PP/128), 256, 65536>>>(Fout);
}

// round 9
// speedup vs baseline: 6.0744x; 1.1000x over previous
#include <cuda_runtime.h>
#include <cuda_fp16.h>
#include <math.h>
#include <stdint.h>

#define PP 8192
#define DDIM 512

// ---- scratch (device globals) ----
__device__ __half g_Qh[PP * DDIM];
__device__ __half g_Kh[PP * DDIM];
__device__ __half g_Fh[PP * DDIM];
__device__ __half g_Vth[DDIM * PP];          // V transposed: [feature][position]
__device__ __half g_Th[(size_t)PP * PP];     // unnormalized exp probs (fp16), 128 MB
__device__ float  g_psum[(size_t)PP * 128];  // per (row, colTile) partial sums
__device__ float  g_norm[PP];
__device__ float  g_tdiag[PP];
__device__ float  g_inv[PP];

// ---------------- helpers ----------------
__device__ __forceinline__ uint32_t s2u(const void* p) {
    return (uint32_t)__cvta_generic_to_shared(p);
}
__device__ __forceinline__ uint32_t f2h2(float a, float b) {
    __half2 h = __floats2half2_rn(a, b);
    return *reinterpret_cast<uint32_t*>(&h);
}
// tile rows of 32 halves (64B), 16B chunks XOR-swizzled
__device__ __forceinline__ int swz64(int r, int c) {
    return r * 64 + ((c ^ ((r >> 1) & 3)) << 4);
}
__device__ __forceinline__ void mma16(float* d, const uint32_t* a, const uint32_t* b) {
    asm volatile(
        "mma.sync.aligned.m16n8k16.row.col.f32.f16.f16.f32 "
        "{%0,%1,%2,%3},{%4,%5,%6,%7},{%8,%9},{%0,%1,%2,%3};"
        : "+f"(d[0]), "+f"(d[1]), "+f"(d[2]), "+f"(d[3])
        : "r"(a[0]), "r"(a[1]), "r"(a[2]), "r"(a[3]), "r"(b[0]), "r"(b[1]));
}
__device__ __forceinline__ void ldsm4(uint32_t addr, uint32_t* r) {
    asm volatile("ldmatrix.sync.aligned.m8n8.x4.shared.b16 {%0,%1,%2,%3}, [%4];"
        : "=r"(r[0]), "=r"(r[1]), "=r"(r[2]), "=r"(r[3]) : "r"(addr));
}
__device__ __forceinline__ void fragA(uint32_t tbase, int R, int ks, int lane, uint32_t* a) {
    int mi = lane >> 3, ri = lane & 7;
    int r = R + ri + (mi & 1) * 8;
    int c = ks * 2 + (mi >> 1);
    ldsm4(tbase + swz64(r, c), a);
}
__device__ __forceinline__ void fragB(uint32_t tbase, int N0, int ks, int lane, uint32_t* b) {
    int mi = lane >> 3, ri = lane & 7;
    int r = N0 + ri + (mi >> 1) * 8;
    int c = ks * 2 + (mi & 1);
    ldsm4(tbase + swz64(r, c), b);
}
// ---- cp.async ----
__device__ __forceinline__ void cpa16(uint32_t dst, const void* src) {
    asm volatile("cp.async.cg.shared.global [%0], [%1], 16;" :: "r"(dst), "l"(src));
}
__device__ __forceinline__ void cp_commit() {
    asm volatile("cp.async.commit_group;" ::: "memory");
}
template<int N>
__device__ __forceinline__ void cp_wait() {
    asm volatile("cp.async.wait_group %0;" :: "n"(N) : "memory");
}

// ------- reg-staged tiles for qkv -------
struct U8 { uint4 a, b; };
__device__ __forceinline__ U8 ldgH(const __half* g, size_t ld, int kb, int tid) {
    int row = tid >> 1, c0 = (tid & 1) * 16;
    const __half* p = g + (size_t)row * ld + kb + c0;
    U8 r; r.a = *(const uint4*)p; r.b = *(const uint4*)(p + 8);
    return r;
}
__device__ __forceinline__ void stsH(char* tile, U8 s, int tid) {
    int row = tid >> 1, c0 = (tid & 1) * 2;
    *(uint4*)(tile + swz64(row, c0))     = s.a;
    *(uint4*)(tile + swz64(row, c0 + 1)) = s.b;
}
struct W8 { float4 a, b; };
__device__ __forceinline__ W8 ldgW(const float* g, int ld, int kb, int tid) {
    int row = tid >> 2, c = tid & 3;
    const float* p = g + (size_t)row * ld + kb + c * 8;
    W8 r; r.a = *(const float4*)p; r.b = *(const float4*)(p + 4);
    return r;
}
__device__ __forceinline__ void stsW(char* tile, W8 s, int tid) {
    int row = tid >> 2, c = tid & 3;
    uint4 h;
    h.x = f2h2(s.a.x, s.a.y); h.y = f2h2(s.a.z, s.a.w);
    h.z = f2h2(s.b.x, s.b.y); h.w = f2h2(s.b.z, s.b.w);
    *(uint4*)(tile + swz64(row, c)) = h;
}

// ============================================================
// Kernel 1: row norms of F + convert F -> g_Fh
// ============================================================
__global__ void norm_cvt_kernel(const float* __restrict__ F)
{
    int row = blockIdx.x, tid = threadIdx.x;   // 128 threads
    const float4* fr = (const float4*)(F + (size_t)row * DDIM);
    float4 v = fr[tid];
    float s = v.x*v.x + v.y*v.y + v.z*v.z + v.w*v.w;
    uint2 h; h.x = f2h2(v.x, v.y); h.y = f2h2(v.z, v.w);
    *(uint2*)(g_Fh + (size_t)row * DDIM + tid * 4) = h;
    #pragma unroll
    for (int o = 16; o > 0; o >>= 1) s += __shfl_xor_sync(0xffffffffu, s, o);
    __shared__ float red[4];
    if ((tid & 31) == 0) red[tid >> 5] = s;
    __syncthreads();
    if (tid == 0) g_norm[row] = red[0] + red[1] + red[2] + red[3];
}

// ============================================================
// Kernel 2: Q/K/V = F @ W^T + b (fp16 mma). Outputs Qh,Kh,Vth.
// ============================================================
__global__ __launch_bounds__(256) void qkv_h(
    const float* __restrict__ Wq, const float* __restrict__ bq,
    const float* __restrict__ Wk, const float* __restrict__ bk,
    const float* __restrict__ Wv, const float* __restrict__ bv)
{
    __shared__ char smem[2 * 20 * 1024];
    const int tid = threadIdx.x, lane = tid & 31, wid = tid >> 5;
    const int wm = wid & 3, wn = wid >> 2;
    const int rowBase = blockIdx.y * 128, colBase = blockIdx.x * 64;

    float aq[2][4][4] = {}, ak[2][4][4] = {}, avv[2][4][4] = {};

    const __half* Fb = g_Fh + (size_t)rowBase * DDIM;
    const float* Qb = Wq + (size_t)colBase * DDIM;
    const float* Kb = Wk + (size_t)colBase * DDIM;
    const float* Vb = Wv + (size_t)colBase * DDIM;

    U8 pf = ldgH(Fb, DDIM, 0, tid);
    W8 pq = ldgW(Qb, DDIM, 0, tid);
    W8 pk = ldgW(Kb, DDIM, 0, tid);
    W8 pv = ldgW(Vb, DDIM, 0, tid);
    char* buf0 = smem; char* buf1 = smem + 20 * 1024;
    stsH(buf0, pf, tid);
    stsW(buf0 +  8192, pq, tid);
    stsW(buf0 + 12288, pk, tid);
    stsW(buf0 + 16384, pv, tid);
    __syncthreads();

    const int NKB = DDIM / 32;   // 16
    for (int kb = 0; kb < NKB; kb++) {
        if (kb + 1 < NKB) {
            int k = (kb + 1) * 32;
            pf = ldgH(Fb, DDIM, k, tid);
            pq = ldgW(Qb, DDIM, k, tid);
            pk = ldgW(Kb, DDIM, k, tid);
            pv = ldgW(Vb, DDIM, k, tid);
        }
        uint32_t su = s2u((kb & 1) ? buf1 : buf0);
        #pragma unroll
        for (int ks = 0; ks < 2; ks++) {
            uint32_t a[2][4];
            fragA(su, wm * 32,      ks, lane, a[0]);
            fragA(su, wm * 32 + 16, ks, lane, a[1]);
            #pragma unroll
            for (int p = 0; p < 2; p++) {
                uint32_t b[4];
                fragB(su + 8192, wn * 32 + p * 16, ks, lane, b);
                #pragma unroll
                for (int tm = 0; tm < 2; tm++) {
                    mma16(aq[tm][2*p],   a[tm], b);
                    mma16(aq[tm][2*p+1], a[tm], b + 2);
                }
                fragB(su + 12288, wn * 32 + p * 16, ks, lane, b);
                #pragma unroll
                for (int tm = 0; tm < 2; tm++) {
                    mma16(ak[tm][2*p],   a[tm], b);
                    mma16(ak[tm][2*p+1], a[tm], b + 2);
                }
                fragB(su + 16384, wn * 32 + p * 16, ks, lane, b);
                #pragma unroll
                for (int tm = 0; tm < 2; tm++) {
                    mma16(avv[tm][2*p],   a[tm], b);
                    mma16(avv[tm][2*p+1], a[tm], b + 2);
                }
            }
        }
        char* nxt = (kb & 1) ? buf0 : buf1;
        if (kb + 1 < NKB) {
            stsH(nxt, pf, tid);
            stsW(nxt +  8192, pq, tid);
            stsW(nxt + 12288, pk, tid);
            stsW(nxt + 16384, pv, tid);
        }
        __syncthreads();
    }

    const int gr = lane >> 2, tg = lane & 3;
    #pragma unroll
    for (int tm = 0; tm < 2; tm++) {
        int r0 = rowBase + wm * 32 + tm * 16 + gr, r1 = r0 + 8;
        #pragma unroll
        for (int tn = 0; tn < 4; tn++) {
            int c = colBase + wn * 32 + tn * 8 + 2 * tg;
            float bq0 = bq[c], bq1 = bq[c+1];
            float bk0 = bk[c], bk1 = bk[c+1];
            float bv0 = bv[c], bv1 = bv[c+1];
            float* A = aq[tm][tn];
            *(uint32_t*)(g_Qh + (size_t)r0 * DDIM + c) = f2h2(A[0] + bq0, A[1] + bq1);
            *(uint32_t*)(g_Qh + (size_t)r1 * DDIM + c) = f2h2(A[2] + bq0, A[3] + bq1);
            A = ak[tm][tn];
            *(uint32_t*)(g_Kh + (size_t)r0 * DDIM + c) = f2h2(A[0] + bk0, A[1] + bk1);
            *(uint32_t*)(g_Kh + (size_t)r1 * DDIM + c) = f2h2(A[2] + bk0, A[3] + bk1);
            A = avv[tm][tn];
            g_Vth[(size_t)c     * PP + r0] = __float2half(A[0] + bv0);
            g_Vth[(size_t)(c+1) * PP + r0] = __float2half(A[1] + bv1);
            g_Vth[(size_t)c     * PP + r1] = __float2half(A[2] + bv0);
            g_Vth[(size_t)(c+1) * PP + r1] = __float2half(A[3] + bv1);
        }
    }
}

// ============================================================
// Kernel 3: tdiag[i] = (Q_i . K_i) / sqrt(d)
// ============================================================
__global__ void diag_kernel()
{
    int row = blockIdx.x, tid = threadIdx.x;   // 128 threads
    const __half* Q = g_Qh + (size_t)row * DDIM + tid * 4;
    const __half* K = g_Kh + (size_t)row * DDIM + tid * 4;
    uint2 qa = *(const uint2*)Q;
    uint2 ka = *(const uint2*)K;
    __half2 q0 = *(__half2*)&qa.x, q1 = *(__half2*)&qa.y;
    __half2 k0 = *(__half2*)&ka.x, k1 = *(__half2*)&ka.y;
    float2 qf0 = __half22float2(q0), qf1 = __half22float2(q1);
    float2 kf0 = __half22float2(k0), kf1 = __half22float2(k1);
    float s = qf0.x*kf0.x + qf0.y*kf0.y + qf1.x*kf1.x + qf1.y*kf1.y;
    #pragma unroll
    for (int o = 16; o > 0; o >>= 1) s += __shfl_xor_sync(0xffffffffu, s, o);
    __shared__ float red[4];
    if ((tid & 31) == 0) red[tid >> 5] = s;
    __syncthreads();
    if (tid == 0)
        g_tdiag[row] = (red[0] + red[1] + red[2] + red[3]) * 0.044194173824159216f;
}

// ============================================================
// Kernel 4: S=QK^T and G=FF^T fused. CTA tile 128x64, warp 32x32.
// 4-stage cp.async (24KB/stage, 96KB). 2 CTAs/SM.
// Epilogue: dist out; E=exp(...)->g_Th; psum -> g_psum.
// ============================================================
__device__ __forceinline__ void lg_issue(uint32_t sbase, int stg, int kb, int tid,
    const __half* Qb, const __half* Fr, const __half* Kb, const __half* Cb)
{
    uint32_t so = sbase + stg * 24576;
    // A-side: Q,F tiles 128x32 (8KB each)
    int row = tid >> 1;
    int ch0 = (tid & 1) * 2;
    size_t offA = (size_t)row * DDIM + kb + ch0 * 8;
    cpa16(so +        swz64(row, ch0),     Qb + offA);
    cpa16(so +        swz64(row, ch0 + 1), Qb + offA + 8);
    cpa16(so + 8192 + swz64(row, ch0),     Fr + offA);
    cpa16(so + 8192 + swz64(row, ch0 + 1), Fr + offA + 8);
    // B-side: K,Fc tiles 64x32 (4KB each)
    int brow = tid >> 2;
    int bch = tid & 3;
    size_t offB = (size_t)brow * DDIM + kb + bch * 8;
    cpa16(so + 16384 + swz64(brow, bch), Kb + offB);
    cpa16(so + 20480 + swz64(brow, bch), Cb + offB);
}

__global__ __launch_bounds__(256, 2) void logits_e(
    const float* __restrict__ lamP, float* __restrict__ dist_out)
{
    extern __shared__ char dsm[];
    __shared__ float ps[128][2];
    const uint32_t sbase = s2u(dsm);
    const int tid = threadIdx.x, lane = tid & 31, wid = tid >> 5;
    const int wm = wid & 3, wn = wid >> 2;
    const int rowBase = blockIdx.y * 128, colBase = blockIdx.x * 64;

    float accS[2][4][4] = {}, accG[2][4][4] = {};

    const __half* Qb = g_Qh + (size_t)rowBase * DDIM;
    const __half* Fr = g_Fh + (size_t)rowBase * DDIM;
    const __half* Kb = g_Kh + (size_t)colBase * DDIM;
    const __half* Cb = g_Fh + (size_t)colBase * DDIM;

    const int NKB = DDIM / 32;   // 16
    #pragma unroll
    for (int s = 0; s < 3; s++) {
        lg_issue(sbase, s, s * 32, tid, Qb, Fr, Kb, Cb);
        cp_commit();
    }

    for (int kb = 0; kb < NKB; kb++) {
        cp_wait<2>();
        __syncthreads();
        if (kb + 3 < NKB)
            lg_issue(sbase, (kb + 3) & 3, (kb + 3) * 32, tid, Qb, Fr, Kb, Cb);
        cp_commit();

        uint32_t su = sbase + (kb & 3) * 24576;
        #pragma unroll
        for (int ks = 0; ks < 2; ks++) {
            {   // S = Q K^T
                uint32_t a[2][4];
                fragA(su, wm * 32,      ks, lane, a[0]);
                fragA(su, wm * 32 + 16, ks, lane, a[1]);
                #pragma unroll
                for (int p = 0; p < 2; p++) {
                    uint32_t b[4];
                    fragB(su + 16384, wn * 32 + p * 16, ks, lane, b);
                    #pragma unroll
                    for (int tm = 0; tm < 2; tm++) {
                        mma16(accS[tm][2*p],   a[tm], b);
                        mma16(accS[tm][2*p+1], a[tm], b + 2);
                    }
                }
            }
            {   // G = F F^T
                uint32_t a[2][4];
                fragA(su + 8192, wm * 32,      ks, lane, a[0]);
                fragA(su + 8192, wm * 32 + 16, ks, lane, a[1]);
                #pragma unroll
                for (int p = 0; p < 2; p++) {
                    uint32_t b[4];
                    fragB(su + 20480, wn * 32 + p * 16, ks, lane, b);
                    #pragma unroll
                    for (int tm = 0; tm < 2; tm++) {
                        mma16(accG[tm][2*p],   a[tm], b);
                        mma16(accG[tm][2*p+1], a[tm], b + 2);
                    }
                }
            }
        }
    }

    const int gr = lane >> 2, tg = lane & 3;
    const float lam = *lamP;
    const float isd = 0.044194173824159216f;  // 1/sqrt(512)
    float rs[2][2];
    #pragma unroll
    for (int tm = 0; tm < 2; tm++) {
        int r0 = rowBase + wm * 32 + tm * 16 + gr, r1 = r0 + 8;
        float n0 = g_norm[r0], n1 = g_norm[r1];
        float td0 = g_tdiag[r0], td1 = g_tdiag[r1];
        float s0 = 0.f, s1 = 0.f;
        #pragma unroll
        for (int tn = 0; tn < 4; tn++) {
            int c = colBase + wn * 32 + tn * 8 + 2 * tg;
            float nc0 = g_norm[c], nc1 = g_norm[c+1];
            float* S = accS[tm][tn];
            float* G = accG[tm][tn];
            float d00 = sqrtf(fmaxf(n0 + nc0 - 2.f * G[0], 0.f));
            float d01 = sqrtf(fmaxf(n0 + nc1 - 2.f * G[1], 0.f));
            float d10 = sqrtf(fmaxf(n1 + nc0 - 2.f * G[2], 0.f));
            float d11 = sqrtf(fmaxf(n1 + nc1 - 2.f * G[3], 0.f));
            size_t o0 = (size_t)r0 * PP + c, o1 = (size_t)r1 * PP + c;
            *(float2*)(dist_out + o0) = make_float2(d00, d01);
            *(float2*)(dist_out + o1) = make_float2(d10, d11);
            float e00 = __expf(fminf(S[0]*isd - lam*d00 - td0, 11.f));
            float e01 = __expf(fminf(S[1]*isd - lam*d01 - td0, 11.f));
            float e10 = __expf(fminf(S[2]*isd - lam*d10 - td1, 11.f));
            float e11 = __expf(fminf(S[3]*isd - lam*d11 - td1, 11.f));
            s0 += e00 + e01;
            s1 += e10 + e11;
            *(uint32_t*)(g_Th + o0) = f2h2(e00, e01);
            *(uint32_t*)(g_Th + o1) = f2h2(e10, e11);
        }
        rs[tm][0] = s0; rs[tm][1] = s1;
    }
    #pragma unroll
    for (int tm = 0; tm < 2; tm++) {
        #pragma unroll
        for (int h = 0; h < 2; h++) {
            float s = rs[tm][h];
            s += __shfl_xor_sync(0xffffffffu, s, 1);
            s += __shfl_xor_sync(0xffffffffu, s, 2);
            if (tg == 0) ps[wm * 32 + tm * 16 + gr + h * 8][wn] = s;
        }
    }
    __syncthreads();
    if (tid < 128)
        g_psum[(size_t)(rowBase + tid) * 128 + blockIdx.x] = ps[tid][0] + ps[tid][1];
}

// ============================================================
// Kernel 5: g_inv[row] = 1 / sum over 128 col-tile partials
// ============================================================
__global__ void rowsum_kernel()
{
    int row = blockIdx.x, lane = threadIdx.x;  // 32 threads
    const float* p = g_psum + (size_t)row * 128;
    float s = p[lane] + p[lane + 32] + p[lane + 64] + p[lane + 96];
    #pragma unroll
    for (int o = 16; o > 0; o >>= 1) s += __shfl_xor_sync(0xffffffffu, s, o);
    if (lane == 0) g_inv[row] = 1.f / s;
}

// ============================================================
// Kernel 6: F_out = (E @ V) * (1/sum). fp16 mma, cp.async 4-stage.
// 2 CTAs/SM.
// ============================================================
__device__ __forceinline__ void av_issue(uint32_t sbase, int stg, int kb, int tid,
    const __half* Ab, const __half* Bb)
{
    int row = tid >> 1;
    int ch0 = (tid & 1) * 2;
    uint32_t so = sbase + stg * 16384;
    size_t off = (size_t)row * PP + kb + ch0 * 8;
    cpa16(so +        swz64(row, ch0),     Ab + off);
    cpa16(so +        swz64(row, ch0 + 1), Ab + off + 8);
    cpa16(so + 8192 + swz64(row, ch0),     Bb + off);
    cpa16(so + 8192 + swz64(row, ch0 + 1), Bb + off + 8);
}

__global__ __launch_bounds__(256, 2) void av_e(float* __restrict__ out)
{
    extern __shared__ char dsm[];
    const uint32_t sbase = s2u(dsm);
    const int tid = threadIdx.x, lane = tid & 31, wid = tid >> 5;
    const int wm = wid & 3, wn = wid >> 2;
    const int rowBase = blockIdx.y * 128, colBase = blockIdx.x * 128;

    float acc[2][8][4] = {};

    const __half* Ab = g_Th  + (size_t)rowBase * PP;
    const __half* Bb = g_Vth + (size_t)colBase * PP;

    const int NKB = PP / 32;   // 256
    #pragma unroll
    for (int s = 0; s < 3; s++) {
        av_issue(sbase, s, s * 32, tid, Ab, Bb);
        cp_commit();
    }

    for (int kb = 0; kb < NKB; kb++) {
        cp_wait<2>();
        __syncthreads();
        if (kb + 3 < NKB)
            av_issue(sbase, (kb + 3) & 3, (kb + 3) * 32, tid, Ab, Bb);
        cp_commit();

        uint32_t su = sbase + (kb & 3) * 16384;
        #pragma unroll
        for (int ks = 0; ks < 2; ks++) {
            uint32_t a[2][4];
            fragA(su, wm * 32,      ks, lane, a[0]);
            fragA(su, wm * 32 + 16, ks, lane, a[1]);
            #pragma unroll
            for (int p = 0; p < 4; p++) {
                uint32_t b[4];
                fragB(su + 8192, wn * 64 + p * 16, ks, lane, b);
                #pragma unroll
                for (int tm = 0; tm < 2; tm++) {
                    mma16(acc[tm][2*p],   a[tm], b);
                    mma16(acc[tm][2*p+1], a[tm], b + 2);
                }
            }
        }
    }

    const int gr = lane >> 2, tg = lane & 3;
    #pragma unroll
    for (int tm = 0; tm < 2; tm++) {
        int r0 = rowBase + wm * 32 + tm * 16 + gr, r1 = r0 + 8;
        float i0 = g_inv[r0], i1 = g_inv[r1];
        #pragma unroll
        for (int tn = 0; tn < 8; tn++) {
            int c = colBase + wn * 64 + tn * 8 + 2 * tg;
            float* A = acc[tm][tn];
            *(float2*)(out + (size_t)r0 * DDIM + c) = make_float2(A[0]*i0, A[1]*i0);
            *(float2*)(out + (size_t)r1 * DDIM + c) = make_float2(A[2]*i1, A[3]*i1);
        }
    }
}

// ============================================================
extern "C" void kernel_launch(void* const* d_in, const int* in_sizes, int n_in,
                              void* d_out, int out_size)
{
    const float* F   = (const float*)d_in[0];
    const float* Wq  = (const float*)d_in[1];
    const float* bq  = (const float*)d_in[2];
    const float* Wk  = (const float*)d_in[3];
    const float* bk  = (const float*)d_in[4];
    const float* Wv  = (const float*)d_in[5];
    const float* bv  = (const float*)d_in[6];
    const float* lam = (const float*)d_in[7];

    float* out  = (float*)d_out;
    float* Fout = out;                        // [P, D]
    float* dist = out + (size_t)PP * DDIM;    // [P, P]

    static bool attr_done = false;
    if (!attr_done) {
        cudaFuncSetAttribute(logits_e, cudaFuncAttributeMaxDynamicSharedMemorySize, 98304);
        cudaFuncSetAttribute(av_e,     cudaFuncAttributeMaxDynamicSharedMemorySize, 65536);
        attr_done = true;
    }

    norm_cvt_kernel<<<PP, 128>>>(F);
    qkv_h<<<dim3(DDIM/64, PP/128), 256>>>(Wq, bq, Wk, bk, Wv, bv);
    diag_kernel<<<PP, 128>>>();
    logits_e<<<dim3(PP/64, PP/128), 256, 98304>>>(lam, dist);
    rowsum_kernel<<<PP, 32>>>();
    av_e<<<dim3(DDIM/128, PP/128), 256, 65536>>>(Fout);
}

// round 10
// speedup vs baseline: 7.1352x; 1.1746x over previous
#include <cuda_runtime.h>
#include <cuda_fp16.h>
#include <math.h>
#include <stdint.h>

#define PP 8192
#define DDIM 512

// ---- scratch (device globals) ----
__device__ __half g_Qh[PP * DDIM];
__device__ __half g_Kh[PP * DDIM];
__device__ __half g_Fh[PP * DDIM];
__device__ __half g_Vth[DDIM * PP];          // V transposed: [feature][position]
__device__ __half g_Th[(size_t)PP * PP];     // unnormalized exp probs (fp16), 128 MB
__device__ float  g_psum[(size_t)PP * 64];   // per (row, colTile) partial sums
__device__ float  g_norm[PP];
__device__ float  g_tdiag[PP];
__device__ float  g_inv[PP];

// ---------------- helpers ----------------
__device__ __forceinline__ uint32_t s2u(const void* p) {
    return (uint32_t)__cvta_generic_to_shared(p);
}
__device__ __forceinline__ uint32_t f2h2(float a, float b) {
    __half2 h = __floats2half2_rn(a, b);
    return *reinterpret_cast<uint32_t*>(&h);
}
// tile rows of 32 halves (64B), 16B chunks XOR-swizzled
__device__ __forceinline__ int swz64(int r, int c) {
    return r * 64 + ((c ^ ((r >> 1) & 3)) << 4);
}
__device__ __forceinline__ void mma16(float* d, const uint32_t* a, const uint32_t* b) {
    asm volatile(
        "mma.sync.aligned.m16n8k16.row.col.f32.f16.f16.f32 "
        "{%0,%1,%2,%3},{%4,%5,%6,%7},{%8,%9},{%0,%1,%2,%3};"
        : "+f"(d[0]), "+f"(d[1]), "+f"(d[2]), "+f"(d[3])
        : "r"(a[0]), "r"(a[1]), "r"(a[2]), "r"(a[3]), "r"(b[0]), "r"(b[1]));
}
__device__ __forceinline__ void ldsm4(uint32_t addr, uint32_t* r) {
    asm volatile("ldmatrix.sync.aligned.m8n8.x4.shared.b16 {%0,%1,%2,%3}, [%4];"
        : "=r"(r[0]), "=r"(r[1]), "=r"(r[2]), "=r"(r[3]) : "r"(addr));
}
__device__ __forceinline__ void fragA(uint32_t tbase, int R, int ks, int lane, uint32_t* a) {
    int mi = lane >> 3, ri = lane & 7;
    int r = R + ri + (mi & 1) * 8;
    int c = ks * 2 + (mi >> 1);
    ldsm4(tbase + swz64(r, c), a);
}
__device__ __forceinline__ void fragB(uint32_t tbase, int N0, int ks, int lane, uint32_t* b) {
    int mi = lane >> 3, ri = lane & 7;
    int r = N0 + ri + (mi >> 1) * 8;
    int c = ks * 2 + (mi & 1);
    ldsm4(tbase + swz64(r, c), b);
}
// ---- cp.async ----
__device__ __forceinline__ void cpa16(uint32_t dst, const void* src) {
    asm volatile("cp.async.cg.shared.global [%0], [%1], 16;" :: "r"(dst), "l"(src));
}
__device__ __forceinline__ void cp_commit() {
    asm volatile("cp.async.commit_group;" ::: "memory");
}
template<int N>
__device__ __forceinline__ void cp_wait() {
    asm volatile("cp.async.wait_group %0;" :: "n"(N) : "memory");
}

// ------- reg-staged tiles for qkv -------
struct U8 { uint4 a, b; };
__device__ __forceinline__ U8 ldgH(const __half* g, size_t ld, int kb, int tid) {
    int row = tid >> 1, c0 = (tid & 1) * 16;
    const __half* p = g + (size_t)row * ld + kb + c0;
    U8 r; r.a = *(const uint4*)p; r.b = *(const uint4*)(p + 8);
    return r;
}
__device__ __forceinline__ void stsH(char* tile, U8 s, int tid) {
    int row = tid >> 1, c0 = (tid & 1) * 2;
    *(uint4*)(tile + swz64(row, c0))     = s.a;
    *(uint4*)(tile + swz64(row, c0 + 1)) = s.b;
}
struct W8 { float4 a, b; };
__device__ __forceinline__ W8 ldgW(const float* g, int ld, int kb, int tid) {
    int row = tid >> 2, c = tid & 3;
    const float* p = g + (size_t)row * ld + kb + c * 8;
    W8 r; r.a = *(const float4*)p; r.b = *(const float4*)(p + 4);
    return r;
}
__device__ __forceinline__ void stsW(char* tile, W8 s, int tid) {
    int row = tid >> 2, c = tid & 3;
    uint4 h;
    h.x = f2h2(s.a.x, s.a.y); h.y = f2h2(s.a.z, s.a.w);
    h.z = f2h2(s.b.x, s.b.y); h.w = f2h2(s.b.z, s.b.w);
    *(uint4*)(tile + swz64(row, c)) = h;
}

// ============================================================
// Kernel 1: row norms of F + convert F -> g_Fh
// ============================================================
__global__ void norm_cvt_kernel(const float* __restrict__ F)
{
    int row = blockIdx.x, tid = threadIdx.x;   // 128 threads
    const float4* fr = (const float4*)(F + (size_t)row * DDIM);
    float4 v = fr[tid];
    float s = v.x*v.x + v.y*v.y + v.z*v.z + v.w*v.w;
    uint2 h; h.x = f2h2(v.x, v.y); h.y = f2h2(v.z, v.w);
    *(uint2*)(g_Fh + (size_t)row * DDIM + tid * 4) = h;
    #pragma unroll
    for (int o = 16; o > 0; o >>= 1) s += __shfl_xor_sync(0xffffffffu, s, o);
    __shared__ float red[4];
    if ((tid & 31) == 0) red[tid >> 5] = s;
    __syncthreads();
    if (tid == 0) g_norm[row] = red[0] + red[1] + red[2] + red[3];
}

// ============================================================
// Kernel 2: Q/K/V = F @ W^T + b (fp16 mma). Outputs Qh,Kh,Vth.
// ============================================================
__global__ __launch_bounds__(256) void qkv_h(
    const float* __restrict__ Wq, const float* __restrict__ bq,
    const float* __restrict__ Wk, const float* __restrict__ bk,
    const float* __restrict__ Wv, const float* __restrict__ bv)
{
    __shared__ char smem[2 * 20 * 1024];
    const int tid = threadIdx.x, lane = tid & 31, wid = tid >> 5;
    const int wm = wid & 3, wn = wid >> 2;
    const int rowBase = blockIdx.y * 128, colBase = blockIdx.x * 64;

    float aq[2][4][4] = {}, ak[2][4][4] = {}, avv[2][4][4] = {};

    const __half* Fb = g_Fh + (size_t)rowBase * DDIM;
    const float* Qb = Wq + (size_t)colBase * DDIM;
    const float* Kb = Wk + (size_t)colBase * DDIM;
    const float* Vb = Wv + (size_t)colBase * DDIM;

    U8 pf = ldgH(Fb, DDIM, 0, tid);
    W8 pq = ldgW(Qb, DDIM, 0, tid);
    W8 pk = ldgW(Kb, DDIM, 0, tid);
    W8 pv = ldgW(Vb, DDIM, 0, tid);
    char* buf0 = smem; char* buf1 = smem + 20 * 1024;
    stsH(buf0, pf, tid);
    stsW(buf0 +  8192, pq, tid);
    stsW(buf0 + 12288, pk, tid);
    stsW(buf0 + 16384, pv, tid);
    __syncthreads();

    const int NKB = DDIM / 32;   // 16
    for (int kb = 0; kb < NKB; kb++) {
        if (kb + 1 < NKB) {
            int k = (kb + 1) * 32;
            pf = ldgH(Fb, DDIM, k, tid);
            pq = ldgW(Qb, DDIM, k, tid);
            pk = ldgW(Kb, DDIM, k, tid);
            pv = ldgW(Vb, DDIM, k, tid);
        }
        uint32_t su = s2u((kb & 1) ? buf1 : buf0);
        #pragma unroll
        for (int ks = 0; ks < 2; ks++) {
            uint32_t a[2][4];
            fragA(su, wm * 32,      ks, lane, a[0]);
            fragA(su, wm * 32 + 16, ks, lane, a[1]);
            #pragma unroll
            for (int p = 0; p < 2; p++) {
                uint32_t b[4];
                fragB(su + 8192, wn * 32 + p * 16, ks, lane, b);
                #pragma unroll
                for (int tm = 0; tm < 2; tm++) {
                    mma16(aq[tm][2*p],   a[tm], b);
                    mma16(aq[tm][2*p+1], a[tm], b + 2);
                }
                fragB(su + 12288, wn * 32 + p * 16, ks, lane, b);
                #pragma unroll
                for (int tm = 0; tm < 2; tm++) {
                    mma16(ak[tm][2*p],   a[tm], b);
                    mma16(ak[tm][2*p+1], a[tm], b + 2);
                }
                fragB(su + 16384, wn * 32 + p * 16, ks, lane, b);
                #pragma unroll
                for (int tm = 0; tm < 2; tm++) {
                    mma16(avv[tm][2*p],   a[tm], b);
                    mma16(avv[tm][2*p+1], a[tm], b + 2);
                }
            }
        }
        char* nxt = (kb & 1) ? buf0 : buf1;
        if (kb + 1 < NKB) {
            stsH(nxt, pf, tid);
            stsW(nxt +  8192, pq, tid);
            stsW(nxt + 12288, pk, tid);
            stsW(nxt + 16384, pv, tid);
        }
        __syncthreads();
    }

    const int gr = lane >> 2, tg = lane & 3;
    #pragma unroll
    for (int tm = 0; tm < 2; tm++) {
        int r0 = rowBase + wm * 32 + tm * 16 + gr, r1 = r0 + 8;
        #pragma unroll
        for (int tn = 0; tn < 4; tn++) {
            int c = colBase + wn * 32 + tn * 8 + 2 * tg;
            float bq0 = bq[c], bq1 = bq[c+1];
            float bk0 = bk[c], bk1 = bk[c+1];
            float bv0 = bv[c], bv1 = bv[c+1];
            float* A = aq[tm][tn];
            *(uint32_t*)(g_Qh + (size_t)r0 * DDIM + c) = f2h2(A[0] + bq0, A[1] + bq1);
            *(uint32_t*)(g_Qh + (size_t)r1 * DDIM + c) = f2h2(A[2] + bq0, A[3] + bq1);
            A = ak[tm][tn];
            *(uint32_t*)(g_Kh + (size_t)r0 * DDIM + c) = f2h2(A[0] + bk0, A[1] + bk1);
            *(uint32_t*)(g_Kh + (size_t)r1 * DDIM + c) = f2h2(A[2] + bk0, A[3] + bk1);
            A = avv[tm][tn];
            g_Vth[(size_t)c     * PP + r0] = __float2half(A[0] + bv0);
            g_Vth[(size_t)(c+1) * PP + r0] = __float2half(A[1] + bv1);
            g_Vth[(size_t)c     * PP + r1] = __float2half(A[2] + bv0);
            g_Vth[(size_t)(c+1) * PP + r1] = __float2half(A[3] + bv1);
        }
    }
}

// ============================================================
// Kernel 3: tdiag[i] = (Q_i . K_i) / sqrt(d)
// ============================================================
__global__ void diag_kernel()
{
    int row = blockIdx.x, tid = threadIdx.x;   // 128 threads
    const __half* Q = g_Qh + (size_t)row * DDIM + tid * 4;
    const __half* K = g_Kh + (size_t)row * DDIM + tid * 4;
    uint2 qa = *(const uint2*)Q;
    uint2 ka = *(const uint2*)K;
    __half2 q0 = *(__half2*)&qa.x, q1 = *(__half2*)&qa.y;
    __half2 k0 = *(__half2*)&ka.x, k1 = *(__half2*)&ka.y;
    float2 qf0 = __half22float2(q0), qf1 = __half22float2(q1);
    float2 kf0 = __half22float2(k0), kf1 = __half22float2(k1);
    float s = qf0.x*kf0.x + qf0.y*kf0.y + qf1.x*kf1.x + qf1.y*kf1.y;
    #pragma unroll
    for (int o = 16; o > 0; o >>= 1) s += __shfl_xor_sync(0xffffffffu, s, o);
    __shared__ float red[4];
    if ((tid & 31) == 0) red[tid >> 5] = s;
    __syncthreads();
    if (tid == 0)
        g_tdiag[row] = (red[0] + red[1] + red[2] + red[3]) * 0.044194173824159216f;
}

// ============================================================
// Kernel 4: dist via G=FF^T, lower-triangle tiles only (bx<=by).
// 128x128 tile, warp 32x64, 4-stage cp.async (16KB/stage).
// Writes dist[r][c] direct + mirrored dist[c][r] via smem transpose.
// ============================================================
__device__ __forceinline__ void ds_issue(uint32_t sbase, int stg, int kb, int tid,
    const __half* Fr, const __half* Fc)
{
    int row = tid >> 1;
    int ch0 = (tid & 1) * 2;
    uint32_t so = sbase + stg * 16384;
    size_t off = (size_t)row * DDIM + kb + ch0 * 8;
    cpa16(so +        swz64(row, ch0),     Fr + off);
    cpa16(so +        swz64(row, ch0 + 1), Fr + off + 8);
    cpa16(so + 8192 + swz64(row, ch0),     Fc + off);
    cpa16(so + 8192 + swz64(row, ch0 + 1), Fc + off + 8);
}

__global__ __launch_bounds__(256, 2) void dist_sym(float* __restrict__ dist_out)
{
    if (blockIdx.x > blockIdx.y) return;
    extern __shared__ char dsm[];
    const uint32_t sbase = s2u(dsm);
    const int tid = threadIdx.x, lane = tid & 31, wid = tid >> 5;
    const int wm = wid & 3, wn = wid >> 2;
    const int rowBase = blockIdx.y * 128, colBase = blockIdx.x * 128;

    float acc[2][8][4] = {};

    const __half* Fr = g_Fh + (size_t)rowBase * DDIM;
    const __half* Fc = g_Fh + (size_t)colBase * DDIM;

    const int NKB = DDIM / 32;   // 16
    #pragma unroll
    for (int s = 0; s < 3; s++) {
        ds_issue(sbase, s, s * 32, tid, Fr, Fc);
        cp_commit();
    }

    for (int kb = 0; kb < NKB; kb++) {
        cp_wait<2>();
        __syncthreads();
        if (kb + 3 < NKB)
            ds_issue(sbase, (kb + 3) & 3, (kb + 3) * 32, tid, Fr, Fc);
        cp_commit();

        uint32_t su = sbase + (kb & 3) * 16384;
        #pragma unroll
        for (int ks = 0; ks < 2; ks++) {
            uint32_t a[2][4];
            fragA(su, wm * 32,      ks, lane, a[0]);
            fragA(su, wm * 32 + 16, ks, lane, a[1]);
            #pragma unroll
            for (int p = 0; p < 4; p++) {
                uint32_t b[4];
                fragB(su + 8192, wn * 64 + p * 16, ks, lane, b);
                #pragma unroll
                for (int tm = 0; tm < 2; tm++) {
                    mma16(acc[tm][2*p],   a[tm], b);
                    mma16(acc[tm][2*p+1], a[tm], b + 2);
                }
            }
        }
    }
    cp_wait<0>();
    __syncthreads();

    // epilogue: dist = sqrt(max(nr + nc - 2G, 0)); direct write + smem transpose
    float* st = (float*)dsm;   // [128][132] floats
    const int gr = lane >> 2, tg = lane & 3;
    #pragma unroll
    for (int tm = 0; tm < 2; tm++) {
        int rl0 = wm * 32 + tm * 16 + gr, rl1 = rl0 + 8;
        int r0 = rowBase + rl0, r1 = rowBase + rl1;
        float n0 = g_norm[r0], n1 = g_norm[r1];
        #pragma unroll
        for (int tn = 0; tn < 8; tn++) {
            int cl = wn * 64 + tn * 8 + 2 * tg;
            int c = colBase + cl;
            float nc0 = g_norm[c], nc1 = g_norm[c+1];
            float* A = acc[tm][tn];
            float d00 = sqrtf(fmaxf(n0 + nc0 - 2.f * A[0], 0.f));
            float d01 = sqrtf(fmaxf(n0 + nc1 - 2.f * A[1], 0.f));
            float d10 = sqrtf(fmaxf(n1 + nc0 - 2.f * A[2], 0.f));
            float d11 = sqrtf(fmaxf(n1 + nc1 - 2.f * A[3], 0.f));
            *(float2*)(dist_out + (size_t)r0 * PP + c) = make_float2(d00, d01);
            *(float2*)(dist_out + (size_t)r1 * PP + c) = make_float2(d10, d11);
            st[(cl    ) * 132 + rl0] = d00;
            st[(cl + 1) * 132 + rl0] = d01;
            st[(cl    ) * 132 + rl1] = d10;
            st[(cl + 1) * 132 + rl1] = d11;
        }
    }
    __syncthreads();
    if (blockIdx.x != blockIdx.y) {
        int i = tid >> 1;                 // 0..127: row of transposed tile
        int j0 = (tid & 1) * 64;
        const float* srow = st + i * 132 + j0;
        float* orow = dist_out + (size_t)(colBase + i) * PP + rowBase + j0;
        #pragma unroll
        for (int j = 0; j < 64; j += 4)
            *(float4*)(orow + j) = *(const float4*)(srow + j);
    }
}

// ============================================================
// Kernel 5: S=QK^T (128x128 tile, warp 32x64). Epilogue reads dist,
// computes E=exp(S*isd - lam*d - td) -> g_Th, psum -> g_psum.
// ============================================================
__device__ __forceinline__ void ls_issue(uint32_t sbase, int stg, int kb, int tid,
    const __half* Qb, const __half* Kb)
{
    int row = tid >> 1;
    int ch0 = (tid & 1) * 2;
    uint32_t so = sbase + stg * 16384;
    size_t off = (size_t)row * DDIM + kb + ch0 * 8;
    cpa16(so +        swz64(row, ch0),     Qb + off);
    cpa16(so +        swz64(row, ch0 + 1), Qb + off + 8);
    cpa16(so + 8192 + swz64(row, ch0),     Kb + off);
    cpa16(so + 8192 + swz64(row, ch0 + 1), Kb + off + 8);
}

__global__ __launch_bounds__(256, 2) void logits_s(
    const float* __restrict__ lamP, const float* __restrict__ dist_in)
{
    extern __shared__ char dsm[];
    __shared__ float ps[128][2];
    const uint32_t sbase = s2u(dsm);
    const int tid = threadIdx.x, lane = tid & 31, wid = tid >> 5;
    const int wm = wid & 3, wn = wid >> 2;
    const int rowBase = blockIdx.y * 128, colBase = blockIdx.x * 128;

    float acc[2][8][4] = {};

    const __half* Qb = g_Qh + (size_t)rowBase * DDIM;
    const __half* Kb = g_Kh + (size_t)colBase * DDIM;

    const int NKB = DDIM / 32;   // 16
    #pragma unroll
    for (int s = 0; s < 3; s++) {
        ls_issue(sbase, s, s * 32, tid, Qb, Kb);
        cp_commit();
    }

    for (int kb = 0; kb < NKB; kb++) {
        cp_wait<2>();
        __syncthreads();
        if (kb + 3 < NKB)
            ls_issue(sbase, (kb + 3) & 3, (kb + 3) * 32, tid, Qb, Kb);
        cp_commit();

        uint32_t su = sbase + (kb & 3) * 16384;
        #pragma unroll
        for (int ks = 0; ks < 2; ks++) {
            uint32_t a[2][4];
            fragA(su, wm * 32,      ks, lane, a[0]);
            fragA(su, wm * 32 + 16, ks, lane, a[1]);
            #pragma unroll
            for (int p = 0; p < 4; p++) {
                uint32_t b[4];
                fragB(su + 8192, wn * 64 + p * 16, ks, lane, b);
                #pragma unroll
                for (int tm = 0; tm < 2; tm++) {
                    mma16(acc[tm][2*p],   a[tm], b);
                    mma16(acc[tm][2*p+1], a[tm], b + 2);
                }
            }
        }
    }

    const int gr = lane >> 2, tg = lane & 3;
    const float lam = *lamP;
    const float isd = 0.044194173824159216f;  // 1/sqrt(512)
    float rs[2][2];
    #pragma unroll
    for (int tm = 0; tm < 2; tm++) {
        int r0 = rowBase + wm * 32 + tm * 16 + gr, r1 = r0 + 8;
        float td0 = g_tdiag[r0], td1 = g_tdiag[r1];
        float s0 = 0.f, s1 = 0.f;
        #pragma unroll
        for (int tn = 0; tn < 8; tn++) {
            int c = colBase + wn * 64 + tn * 8 + 2 * tg;
            size_t o0 = (size_t)r0 * PP + c, o1 = (size_t)r1 * PP + c;
            float2 dd0 = *(const float2*)(dist_in + o0);
            float2 dd1 = *(const float2*)(dist_in + o1);
            float* S = acc[tm][tn];
            float e00 = __expf(fminf(S[0]*isd - lam*dd0.x - td0, 11.f));
            float e01 = __expf(fminf(S[1]*isd - lam*dd0.y - td0, 11.f));
            float e10 = __expf(fminf(S[2]*isd - lam*dd1.x - td1, 11.f));
            float e11 = __expf(fminf(S[3]*isd - lam*dd1.y - td1, 11.f));
            s0 += e00 + e01;
            s1 += e10 + e11;
            *(uint32_t*)(g_Th + o0) = f2h2(e00, e01);
            *(uint32_t*)(g_Th + o1) = f2h2(e10, e11);
        }
        rs[tm][0] = s0; rs[tm][1] = s1;
    }
    #pragma unroll
    for (int tm = 0; tm < 2; tm++) {
        #pragma unroll
        for (int h = 0; h < 2; h++) {
            float s = rs[tm][h];
            s += __shfl_xor_sync(0xffffffffu, s, 1);
            s += __shfl_xor_sync(0xffffffffu, s, 2);
            if (tg == 0) ps[wm * 32 + tm * 16 + gr + h * 8][wn] = s;
        }
    }
    __syncthreads();
    if (tid < 128)
        g_psum[(size_t)(rowBase + tid) * 64 + blockIdx.x] = ps[tid][0] + ps[tid][1];
}

// ============================================================
// Kernel 6: g_inv[row] = 1 / sum over 64 col-tile partials
// ============================================================
__global__ void rowsum_kernel()
{
    int row = blockIdx.x, lane = threadIdx.x;  // 32 threads
    const float* p = g_psum + (size_t)row * 64;
    float s = p[lane] + p[lane + 32];
    #pragma unroll
    for (int o = 16; o > 0; o >>= 1) s += __shfl_xor_sync(0xffffffffu, s, o);
    if (lane == 0) g_inv[row] = 1.f / s;
}

// ============================================================
// Kernel 7: F_out = (E @ V) * (1/sum). fp16 mma, cp.async 4-stage.
// ============================================================
__device__ __forceinline__ void av_issue(uint32_t sbase, int stg, int kb, int tid,
    const __half* Ab, const __half* Bb)
{
    int row = tid >> 1;
    int ch0 = (tid & 1) * 2;
    uint32_t so = sbase + stg * 16384;
    size_t off = (size_t)row * PP + kb + ch0 * 8;
    cpa16(so +        swz64(row, ch0),     Ab + off);
    cpa16(so +        swz64(row, ch0 + 1), Ab + off + 8);
    cpa16(so + 8192 + swz64(row, ch0),     Bb + off);
    cpa16(so + 8192 + swz64(row, ch0 + 1), Bb + off + 8);
}

__global__ __launch_bounds__(256, 2) void av_e(float* __restrict__ out)
{
    extern __shared__ char dsm[];
    const uint32_t sbase = s2u(dsm);
    const int tid = threadIdx.x, lane = tid & 31, wid = tid >> 5;
    const int wm = wid & 3, wn = wid >> 2;
    const int rowBase = blockIdx.y * 128, colBase = blockIdx.x * 128;

    float acc[2][8][4] = {};

    const __half* Ab = g_Th  + (size_t)rowBase * PP;
    const __half* Bb = g_Vth + (size_t)colBase * PP;

    const int NKB = PP / 32;   // 256
    #pragma unroll
    for (int s = 0; s < 3; s++) {
        av_issue(sbase, s, s * 32, tid, Ab, Bb);
        cp_commit();
    }

    for (int kb = 0; kb < NKB; kb++) {
        cp_wait<2>();
        __syncthreads();
        if (kb + 3 < NKB)
            av_issue(sbase, (kb + 3) & 3, (kb + 3) * 32, tid, Ab, Bb);
        cp_commit();

        uint32_t su = sbase + (kb & 3) * 16384;
        #pragma unroll
        for (int ks = 0; ks < 2; ks++) {
            uint32_t a[2][4];
            fragA(su, wm * 32,      ks, lane, a[0]);
            fragA(su, wm * 32 + 16, ks, lane, a[1]);
            #pragma unroll
            for (int p = 0; p < 4; p++) {
                uint32_t b[4];
                fragB(su + 8192, wn * 64 + p * 16, ks, lane, b);
                #pragma unroll
                for (int tm = 0; tm < 2; tm++) {
                    mma16(acc[tm][2*p],   a[tm], b);
                    mma16(acc[tm][2*p+1], a[tm], b + 2);
                }
            }
        }
    }

    const int gr = lane >> 2, tg = lane & 3;
    #pragma unroll
    for (int tm = 0; tm < 2; tm++) {
        int r0 = rowBase + wm * 32 + tm * 16 + gr, r1 = r0 + 8;
        float i0 = g_inv[r0], i1 = g_inv[r1];
        #pragma unroll
        for (int tn = 0; tn < 8; tn++) {
            int c = colBase + wn * 64 + tn * 8 + 2 * tg;
            float* A = acc[tm][tn];
            *(float2*)(out + (size_t)r0 * DDIM + c) = make_float2(A[0]*i0, A[1]*i0);
            *(float2*)(out + (size_t)r1 * DDIM + c) = make_float2(A[2]*i1, A[3]*i1);
        }
    }
}

// ============================================================
extern "C" void kernel_launch(void* const* d_in, const int* in_sizes, int n_in,
                              void* d_out, int out_size)
{
    const float* F   = (const float*)d_in[0];
    const float* Wq  = (const float*)d_in[1];
    const float* bq  = (const float*)d_in[2];
    const float* Wk  = (const float*)d_in[3];
    const float* bk  = (const float*)d_in[4];
    const float* Wv  = (const float*)d_in[5];
    const float* bv  = (const float*)d_in[6];
    const float* lam = (const float*)d_in[7];

    float* out  = (float*)d_out;
    float* Fout = out;                        // [P, D]
    float* dist = out + (size_t)PP * DDIM;    // [P, P]

    static bool attr_done = false;
    if (!attr_done) {
        cudaFuncSetAttribute(dist_sym, cudaFuncAttributeMaxDynamicSharedMemorySize, 69632);
        cudaFuncSetAttribute(logits_s, cudaFuncAttributeMaxDynamicSharedMemorySize, 65536);
        cudaFuncSetAttribute(av_e,     cudaFuncAttributeMaxDynamicSharedMemorySize, 65536);
        attr_done = true;
    }

    norm_cvt_kernel<<<PP, 128>>>(F);
    qkv_h<<<dim3(DDIM/64, PP/128), 256>>>(Wq, bq, Wk, bk, Wv, bv);
    diag_kernel<<<PP, 128>>>();
    dist_sym<<<dim3(PP/128, PP/128), 256, 69632>>>(dist);
    logits_s<<<dim3(PP/128, PP/128), 256, 65536>>>(lam, dist);
    rowsum_kernel<<<PP, 32>>>();
    av_e<<<dim3(DDIM/128, PP/128), 256, 65536>>>(Fout);
}